// round 1
// baseline (speedup 1.0000x reference)
#include <cuda_runtime.h>
#include <math.h>

#define BATCH 8
#define NTOK  1024
#define EMB   1024
#define HEADS 16
#define DHEAD 64
#define ATT_SCALE 0.125f

// Scratch (device globals; no allocation allowed)
__device__ float g_qkv[(size_t)BATCH * NTOK * 3 * EMB];   // 96 MB
__device__ float g_att[(size_t)BATCH * NTOK * EMB];       // 32 MB

// ---------------------------------------------------------------------------
// SGEMM-NT: C[M,N] = A[M,K] * B[N,K]^T (+ bias[N])
// BM=BN=128, BK=16, 256 threads, 8x8 micro-tile per thread.
// ---------------------------------------------------------------------------
template<bool ADD_BIAS>
__global__ __launch_bounds__(256)
void sgemm_nt(const float* __restrict__ A, const float* __restrict__ B,
              const float* __restrict__ bias, float* __restrict__ C,
              int M, int N, int K)
{
    const int BM = 128, BN = 128, BK = 16;
    __shared__ float As[BK][BM];
    __shared__ float Bs[BK][BN];

    int tid  = threadIdx.x;
    int tr   = tid >> 4;          // 0..15  (M dir)
    int tc   = tid & 15;          // 0..15  (N dir)
    int row0 = blockIdx.y * BM;
    int col0 = blockIdx.x * BN;

    float acc[8][8];
    #pragma unroll
    for (int i = 0; i < 8; i++)
        #pragma unroll
        for (int j = 0; j < 8; j++)
            acc[i][j] = 0.0f;

    int lr = tid >> 2;            // 0..63 : tile row
    int lc = (tid & 3) << 2;      // 0,4,8,12 : k-col (float4)

    const float* Ag = A + (size_t)(row0 + lr) * K + lc;
    const float* Bg = B + (size_t)(col0 + lr) * K + lc;

    for (int k0 = 0; k0 < K; k0 += BK) {
        #pragma unroll
        for (int p = 0; p < 2; p++) {
            float4 v = *(const float4*)(Ag + (size_t)p * 64 * K + k0);
            int r = lr + p * 64;
            As[lc + 0][r] = v.x; As[lc + 1][r] = v.y;
            As[lc + 2][r] = v.z; As[lc + 3][r] = v.w;
            float4 w = *(const float4*)(Bg + (size_t)p * 64 * K + k0);
            Bs[lc + 0][r] = w.x; Bs[lc + 1][r] = w.y;
            Bs[lc + 2][r] = w.z; Bs[lc + 3][r] = w.w;
        }
        __syncthreads();

        #pragma unroll
        for (int kk = 0; kk < BK; kk++) {
            float a[8], b[8];
            *(float4*)&a[0] = *(const float4*)&As[kk][tr * 8];
            *(float4*)&a[4] = *(const float4*)&As[kk][tr * 8 + 4];
            *(float4*)&b[0] = *(const float4*)&Bs[kk][tc * 8];
            *(float4*)&b[4] = *(const float4*)&Bs[kk][tc * 8 + 4];
            #pragma unroll
            for (int i = 0; i < 8; i++)
                #pragma unroll
                for (int j = 0; j < 8; j++)
                    acc[i][j] = fmaf(a[i], b[j], acc[i][j]);
        }
        __syncthreads();
    }

    float bv[8];
    if (ADD_BIAS) {
        *(float4*)&bv[0] = *(const float4*)&bias[col0 + tc * 8];
        *(float4*)&bv[4] = *(const float4*)&bias[col0 + tc * 8 + 4];
    }

    #pragma unroll
    for (int i = 0; i < 8; i++) {
        size_t crow = (size_t)(row0 + tr * 8 + i) * N + col0 + tc * 8;
        #pragma unroll
        for (int q = 0; q < 2; q++) {
            float4 v;
            v.x = acc[i][q * 4 + 0]; v.y = acc[i][q * 4 + 1];
            v.z = acc[i][q * 4 + 2]; v.w = acc[i][q * 4 + 3];
            if (ADD_BIAS) {
                v.x += bv[q * 4 + 0]; v.y += bv[q * 4 + 1];
                v.z += bv[q * 4 + 2]; v.w += bv[q * 4 + 3];
            }
            *(float4*)&C[crow + q * 4] = v;
        }
    }
}

// ---------------------------------------------------------------------------
// Flash-style attention. One CTA = (64-query tile, head, batch).
// 256 threads as 16x16; each thread owns a 4(q-row) x 4 micro-tile.
// Online softmax, bias gathered via bias_idxs -> smem-cached per-head row.
// ---------------------------------------------------------------------------
__global__ __launch_bounds__(256)
void attn_kernel(const float* __restrict__ biases,
                 const int*   __restrict__ bidx,
                 float*       __restrict__ outp)
{
    extern __shared__ float sm[];
    float* Qs  = sm;                  // [64][64]
    float* KVs = Qs + 64 * 64;        // [64][65]  (K row-major / V transposed)
    float* Ps  = KVs + 64 * 65;       // [64][64]
    float* bs  = Ps + 64 * 64;        // [1024] per-head bias row

    int tid = threadIdx.x;
    int q0  = blockIdx.x * 64;
    int h   = blockIdx.y;
    int b   = blockIdx.z;

    const float* base = g_qkv + (size_t)b * NTOK * 3 * EMB;

    for (int i = tid; i < 1024; i += 256)
        bs[i] = biases[h * 1024 + i];

    for (int i = tid; i < 64 * 64; i += 256) {
        int r = i >> 6, c = i & 63;
        Qs[i] = base[(size_t)(q0 + r) * (3 * EMB) + h * DHEAD + c];
    }

    int ty = tid >> 4, tx = tid & 15;

    float m[4], l[4], acc[4][4];
    #pragma unroll
    for (int i = 0; i < 4; i++) {
        m[i] = -1e30f; l[i] = 0.0f;
        #pragma unroll
        for (int j = 0; j < 4; j++) acc[i][j] = 0.0f;
    }
    __syncthreads();

    for (int kv0 = 0; kv0 < NTOK; kv0 += 64) {
        // K tile: KVs[kv_row][d], pad 65
        for (int i = tid; i < 64 * 64; i += 256) {
            int r = i >> 6, c = i & 63;
            KVs[r * 65 + c] = base[(size_t)(kv0 + r) * (3 * EMB) + EMB + h * DHEAD + c];
        }
        __syncthreads();

        // S = Q * K^T
        float s[4][4];
        #pragma unroll
        for (int i = 0; i < 4; i++)
            #pragma unroll
            for (int j = 0; j < 4; j++) s[i][j] = 0.0f;

        #pragma unroll 8
        for (int kk = 0; kk < 64; kk++) {
            float a[4], bb[4];
            #pragma unroll
            for (int i = 0; i < 4; i++) a[i]  = Qs[(ty * 4 + i) * 64 + kk];
            #pragma unroll
            for (int j = 0; j < 4; j++) bb[j] = KVs[(tx * 4 + j) * 65 + kk];
            #pragma unroll
            for (int i = 0; i < 4; i++)
                #pragma unroll
                for (int j = 0; j < 4; j++)
                    s[i][j] = fmaf(a[i], bb[j], s[i][j]);
        }

        // scale + bias gather
        #pragma unroll
        for (int i = 0; i < 4; i++) {
            int gi = q0 + ty * 4 + i;
            #pragma unroll
            for (int j = 0; j < 4; j++) {
                int gj  = kv0 + tx * 4 + j;
                int idx = bidx[(size_t)gi * NTOK + gj];
                s[i][j] = fmaf(s[i][j], ATT_SCALE, bs[idx]);
            }
        }

        // online softmax per q-row (16 lanes per row within half-warp)
        #pragma unroll
        for (int i = 0; i < 4; i++) {
            float rm = fmaxf(fmaxf(s[i][0], s[i][1]), fmaxf(s[i][2], s[i][3]));
            #pragma unroll
            for (int o = 8; o > 0; o >>= 1)
                rm = fmaxf(rm, __shfl_xor_sync(0xffffffffu, rm, o));
            float mn = fmaxf(m[i], rm);
            float al = __expf(m[i] - mn);
            m[i] = mn;
            float rs = 0.0f;
            #pragma unroll
            for (int j = 0; j < 4; j++) {
                s[i][j] = __expf(s[i][j] - mn);
                rs += s[i][j];
            }
            #pragma unroll
            for (int o = 8; o > 0; o >>= 1)
                rs += __shfl_xor_sync(0xffffffffu, rs, o);
            l[i] = l[i] * al + rs;
            #pragma unroll
            for (int j = 0; j < 4; j++) acc[i][j] *= al;
            float4 pv = make_float4(s[i][0], s[i][1], s[i][2], s[i][3]);
            *(float4*)&Ps[(ty * 4 + i) * 64 + tx * 4] = pv;
        }
        __syncthreads();   // P written, K reads done

        // V tile TRANSPOSED: KVs[d][kv_row], pad 65 (conflict-free on both sides)
        for (int i = tid; i < 64 * 64; i += 256) {
            int r = i >> 6, c = i & 63;
            KVs[c * 65 + r] = base[(size_t)(kv0 + r) * (3 * EMB) + 2 * EMB + h * DHEAD + c];
        }
        __syncthreads();

        // O += P * V
        #pragma unroll 8
        for (int kk = 0; kk < 64; kk++) {
            float a[4], bb[4];
            #pragma unroll
            for (int i = 0; i < 4; i++) a[i]  = Ps[(ty * 4 + i) * 64 + kk];
            #pragma unroll
            for (int j = 0; j < 4; j++) bb[j] = KVs[(tx * 4 + j) * 65 + kk];
            #pragma unroll
            for (int i = 0; i < 4; i++)
                #pragma unroll
                for (int j = 0; j < 4; j++)
                    acc[i][j] = fmaf(a[i], bb[j], acc[i][j]);
        }
        __syncthreads();   // V reads done before next K overwrite
    }

    #pragma unroll
    for (int i = 0; i < 4; i++) {
        float inv = 1.0f / l[i];
        float4 v = make_float4(acc[i][0] * inv, acc[i][1] * inv,
                               acc[i][2] * inv, acc[i][3] * inv);
        *(float4*)&outp[((size_t)(b * NTOK + q0 + ty * 4 + i)) * EMB + h * DHEAD + tx * 4] = v;
    }
}

// ---------------------------------------------------------------------------
extern "C" void kernel_launch(void* const* d_in, const int* in_sizes, int n_in,
                              void* d_out, int out_size)
{
    const float* x    = (const float*)d_in[0];   // (8,1024,1024)
    const float* Wqkv = (const float*)d_in[1];   // (3072,1024)
    const float* ab   = (const float*)d_in[2];   // (16,1024)
    const int*   bidx = (const int*)  d_in[3];   // (1024,1024)
    const float* Wout = (const float*)d_in[4];   // (1024,1024)
    const float* bout = (const float*)d_in[5];   // (1024,)
    float* out = (float*)d_out;

    float *qkv_p = nullptr, *att_p = nullptr;
    cudaGetSymbolAddress((void**)&qkv_p, g_qkv);
    cudaGetSymbolAddress((void**)&att_p, g_att);

    const int M = BATCH * NTOK;

    // 1) QKV projection: [8192,3072] = x[8192,1024] @ Wqkv[3072,1024]^T
    sgemm_nt<false><<<dim3(3 * EMB / 128, M / 128), 256>>>(
        x, Wqkv, nullptr, qkv_p, M, 3 * EMB, EMB);

    // 2) attention
    const int SMEM = (64 * 64 + 64 * 65 + 64 * 64 + 1024) * (int)sizeof(float); // 53504
    cudaFuncSetAttribute(attn_kernel, cudaFuncAttributeMaxDynamicSharedMemorySize, SMEM);
    attn_kernel<<<dim3(NTOK / 64, HEADS, BATCH), 256, SMEM>>>(ab, bidx, att_p);

    // 3) output projection + bias: [8192,1024] = att[8192,1024] @ Wout^T + b
    sgemm_nt<true><<<dim3(EMB / 128, M / 128), 256>>>(
        att_p, Wout, bout, out, M, EMB, EMB);
}

// round 4
// speedup vs baseline: 1.5224x; 1.5224x over previous
#include <cuda_runtime.h>
#include <cuda_bf16.h>
#include <cstdint>
#include <math.h>

#define BATCH 8
#define NTOK  1024
#define EMB   1024
#define HEADS 16
#define DHEAD 64
#define ATT_SCALE 0.125f
#define GK 1024   // inner K of both projections

// ---------------------------------------------------------------------------
// Scratch (device globals; no allocation allowed)
// ---------------------------------------------------------------------------
__device__ float g_qkv[(size_t)BATCH * NTOK * 3 * EMB];   // 96 MB fp32
__device__ float g_att[(size_t)BATCH * NTOK * EMB];       // 32 MB fp32
__device__ __nv_bfloat16 g_xb   [2 * (size_t)BATCH * NTOK * EMB]; // hi|lo
__device__ __nv_bfloat16 g_wqkvb[2 * (size_t)3 * EMB * EMB];
__device__ __nv_bfloat16 g_woutb[2 * (size_t)EMB * EMB];
__device__ __nv_bfloat16 g_attb [2 * (size_t)BATCH * NTOK * EMB];

// ---------------------------------------------------------------------------
// helpers
// ---------------------------------------------------------------------------
__device__ __forceinline__ uint32_t smem_to_u32(const void* p) {
    uint32_t a;
    asm("{ .reg .u64 t; cvta.to.shared.u64 t, %1; cvt.u32.u64 %0, t; }"
        : "=r"(a) : "l"(p));
    return a;
}
#define SMEM_SWIZZLE_128B(o) ((o) ^ (((o) >> 3) & 0x70))

__device__ __forceinline__ void cp_async16(uint32_t saddr, const void* gaddr) {
    asm volatile("cp.async.cg.shared.global [%0], [%1], 16;"
                 :: "r"(saddr), "l"(gaddr));
}
__device__ __forceinline__ void cp_async_commit() {
    asm volatile("cp.async.commit_group;");
}
__device__ __forceinline__ void cp_async_wait_all() {
    asm volatile("cp.async.wait_group 0;");
}
__device__ __forceinline__ void ldmatrix_x4(uint32_t* r, uint32_t addr) {
    asm volatile("ldmatrix.sync.aligned.m8n8.x4.shared.b16 {%0,%1,%2,%3}, [%4];"
                 : "=r"(r[0]), "=r"(r[1]), "=r"(r[2]), "=r"(r[3]) : "r"(addr));
}
__device__ __forceinline__ void mma16816(float* c, const uint32_t* a,
                                         uint32_t b0, uint32_t b1) {
    asm volatile("mma.sync.aligned.m16n8k16.row.col.f32.bf16.bf16.f32 "
                 "{%0,%1,%2,%3}, {%4,%5,%6,%7}, {%8,%9}, {%0,%1,%2,%3};"
                 : "+f"(c[0]), "+f"(c[1]), "+f"(c[2]), "+f"(c[3])
                 : "r"(a[0]), "r"(a[1]), "r"(a[2]), "r"(a[3]), "r"(b0), "r"(b1));
}

// ---------------------------------------------------------------------------
// fp32 -> (bf16 hi, bf16 lo) split
// ---------------------------------------------------------------------------
__global__ __launch_bounds__(256)
void split_f32(const float* __restrict__ s, __nv_bfloat16* __restrict__ hi,
               __nv_bfloat16* __restrict__ lo, int n)
{
    int i = (blockIdx.x * 256 + threadIdx.x) * 4;
    if (i >= n) return;
    float4 v = *(const float4*)(s + i);
    __nv_bfloat16 h0 = __float2bfloat16(v.x);
    __nv_bfloat16 h1 = __float2bfloat16(v.y);
    __nv_bfloat16 h2 = __float2bfloat16(v.z);
    __nv_bfloat16 h3 = __float2bfloat16(v.w);
    __nv_bfloat16 l0 = __float2bfloat16(v.x - __bfloat162float(h0));
    __nv_bfloat16 l1 = __float2bfloat16(v.y - __bfloat162float(h1));
    __nv_bfloat16 l2 = __float2bfloat16(v.z - __bfloat162float(h2));
    __nv_bfloat16 l3 = __float2bfloat16(v.w - __bfloat162float(h3));
    __nv_bfloat162 a = {h0, h1}, b = {h2, h3}, c = {l0, l1}, d = {l2, l3};
    *(__nv_bfloat162*)(hi + i)     = a;
    *(__nv_bfloat162*)(hi + i + 2) = b;
    *(__nv_bfloat162*)(lo + i)     = c;
    *(__nv_bfloat162*)(lo + i + 2) = d;
}

// ---------------------------------------------------------------------------
// mma.sync bf16x3 GEMM-NT: C[M,N] = A[M,GK] * B[N,GK]^T (+bias)
// A,B hi-buffers; lo at +M*GK / +N*GK. Tile 128x128, BK=64, SW128 smem,
// cp.async double buffer, 8 warps (2m x 4n), warp tile 64x32.
// ---------------------------------------------------------------------------
__global__ __launch_bounds__(256)
void gemm_mma(const __nv_bfloat16* __restrict__ A, const __nv_bfloat16* __restrict__ B,
              const float* __restrict__ bias, float* __restrict__ C,
              int M, int N, int addBias)
{
    extern __shared__ char smem[];
    uint32_t sb = smem_to_u32(smem);

    int tid  = threadIdx.x;
    int wid  = tid >> 5, lane = tid & 31;
    int wm   = (wid >> 2) * 64;   // warp m offset in tile
    int wn   = (wid & 3) * 32;    // warp n offset
    int row0 = blockIdx.y * 128, col0 = blockIdx.x * 128;

    float acc[4][4][4];
    #pragma unroll
    for (int i = 0; i < 4; i++)
        #pragma unroll
        for (int j = 0; j < 4; j++)
            #pragma unroll
            for (int k = 0; k < 4; k++) acc[i][j][k] = 0.0f;

    const int NCHUNKS = 48;    // 3 segments x (1024/64)

    int lr = tid >> 1;                 // 0..127 : tile row (2 threads/row)
    int lc = (tid & 1) << 2;           // 0 or 4 : 16B-chunk pair start

    // issue loads of chunk ci into buffer buf
    auto load_chunk = [&](int ci, int buf) {
        int seg = ci >> 4;
        int k0  = (ci & 15) << 6;
        const __nv_bfloat16* Ag = A + (seg == 1 ? (size_t)M * GK : 0)
                                    + (size_t)row0 * GK + k0;
        const __nv_bfloat16* Bg = B + (seg == 2 ? (size_t)N * GK : 0)
                                    + (size_t)col0 * GK + k0;
        uint32_t abase = sb + buf * 16384;
        uint32_t bbase = sb + 32768 + buf * 16384;
        #pragma unroll
        for (int c = 0; c < 4; c++) {
            uint32_t off = (uint32_t)lr * 128 + (lc + c) * 16;
            uint32_t sw  = SMEM_SWIZZLE_128B(off);
            cp_async16(abase + sw, Ag + (size_t)lr * GK + (lc + c) * 8);
            cp_async16(bbase + sw, Bg + (size_t)lr * GK + (lc + c) * 8);
        }
        cp_async_commit();
    };

    load_chunk(0, 0);
    cp_async_wait_all();
    __syncthreads();

    int mat = lane >> 3, ri = lane & 7;

    for (int ci = 0; ci < NCHUNKS; ci++) {
        int buf = ci & 1;
        if (ci + 1 < NCHUNKS) load_chunk(ci + 1, buf ^ 1);

        uint32_t abase = sb + buf * 16384;
        uint32_t bbase = sb + 32768 + buf * 16384;

        #pragma unroll
        for (int ks = 0; ks < 4; ks++) {
            uint32_t af[4][4];
            #pragma unroll
            for (int mi = 0; mi < 4; mi++) {
                int row = wm + mi * 16 + (mat & 1) * 8 + ri;
                int kb  = (ks * 16 + (mat >> 1) * 8) * 2;
                ldmatrix_x4(af[mi], abase + SMEM_SWIZZLE_128B((uint32_t)(row * 128 + kb)));
            }
            uint32_t bf[2][4];
            #pragma unroll
            for (int ni = 0; ni < 2; ni++) {
                int n  = wn + ni * 16 + (mat >> 1) * 8 + ri;
                int kb = (ks * 16 + (mat & 1) * 8) * 2;
                ldmatrix_x4(bf[ni], bbase + SMEM_SWIZZLE_128B((uint32_t)(n * 128 + kb)));
            }
            #pragma unroll
            for (int mi = 0; mi < 4; mi++)
                #pragma unroll
                for (int j = 0; j < 4; j++) {
                    int ni = j >> 1, pr = (j & 1) * 2;
                    mma16816(acc[mi][j], af[mi], bf[ni][pr], bf[ni][pr + 1]);
                }
        }
        cp_async_wait_all();
        __syncthreads();
    }

    // epilogue: fragment (t/4 = row-in-8, t%4*2 = col pair)
    int tr = lane >> 2, tc = (lane & 3) * 2;
    #pragma unroll
    for (int mi = 0; mi < 4; mi++) {
        #pragma unroll
        for (int j = 0; j < 4; j++) {
            int col = col0 + wn + j * 8 + tc;
            float bx = 0.f, by = 0.f;
            if (addBias) { bx = bias[col]; by = bias[col + 1]; }
            size_t rlo = (size_t)(row0 + wm + mi * 16 + tr) * N + col;
            size_t rhi = rlo + (size_t)8 * N;
            float2 v0 = make_float2(acc[mi][j][0] + bx, acc[mi][j][1] + by);
            float2 v1 = make_float2(acc[mi][j][2] + bx, acc[mi][j][3] + by);
            *(float2*)(C + rlo) = v0;
            *(float2*)(C + rhi) = v1;
        }
    }
}

// ---------------------------------------------------------------------------
// Flash-style attention (fp32, unchanged)
// ---------------------------------------------------------------------------
__global__ __launch_bounds__(256)
void attn_kernel(const float* __restrict__ biases,
                 const int*   __restrict__ bidx,
                 float*       __restrict__ outp)
{
    extern __shared__ float sm[];
    float* Qs  = sm;
    float* KVs = Qs + 64 * 64;
    float* Ps  = KVs + 64 * 65;
    float* bs  = Ps + 64 * 64;

    int tid = threadIdx.x;
    int q0  = blockIdx.x * 64;
    int h   = blockIdx.y;
    int b   = blockIdx.z;

    const float* base = g_qkv + (size_t)b * NTOK * 3 * EMB;

    for (int i = tid; i < 1024; i += 256)
        bs[i] = biases[h * 1024 + i];
    for (int i = tid; i < 64 * 64; i += 256) {
        int r = i >> 6, c = i & 63;
        Qs[i] = base[(size_t)(q0 + r) * (3 * EMB) + h * DHEAD + c];
    }

    int ty = tid >> 4, tx = tid & 15;
    float m[4], l[4], acc[4][4];
    #pragma unroll
    for (int i = 0; i < 4; i++) {
        m[i] = -1e30f; l[i] = 0.0f;
        #pragma unroll
        for (int j = 0; j < 4; j++) acc[i][j] = 0.0f;
    }
    __syncthreads();

    for (int kv0 = 0; kv0 < NTOK; kv0 += 64) {
        for (int i = tid; i < 64 * 64; i += 256) {
            int r = i >> 6, c = i & 63;
            KVs[r * 65 + c] = base[(size_t)(kv0 + r) * (3 * EMB) + EMB + h * DHEAD + c];
        }
        __syncthreads();

        float s[4][4];
        #pragma unroll
        for (int i = 0; i < 4; i++)
            #pragma unroll
            for (int j = 0; j < 4; j++) s[i][j] = 0.0f;

        #pragma unroll 8
        for (int kk = 0; kk < 64; kk++) {
            float a[4], bb[4];
            #pragma unroll
            for (int i = 0; i < 4; i++) a[i]  = Qs[(ty * 4 + i) * 64 + kk];
            #pragma unroll
            for (int j = 0; j < 4; j++) bb[j] = KVs[(tx * 4 + j) * 65 + kk];
            #pragma unroll
            for (int i = 0; i < 4; i++)
                #pragma unroll
                for (int j = 0; j < 4; j++)
                    s[i][j] = fmaf(a[i], bb[j], s[i][j]);
        }

        #pragma unroll
        for (int i = 0; i < 4; i++) {
            int gi = q0 + ty * 4 + i;
            #pragma unroll
            for (int j = 0; j < 4; j++) {
                int gj  = kv0 + tx * 4 + j;
                int idx = bidx[(size_t)gi * NTOK + gj];
                s[i][j] = fmaf(s[i][j], ATT_SCALE, bs[idx]);
            }
        }

        #pragma unroll
        for (int i = 0; i < 4; i++) {
            float rm = fmaxf(fmaxf(s[i][0], s[i][1]), fmaxf(s[i][2], s[i][3]));
            #pragma unroll
            for (int o = 8; o > 0; o >>= 1)
                rm = fmaxf(rm, __shfl_xor_sync(0xffffffffu, rm, o));
            float mn = fmaxf(m[i], rm);
            float al = __expf(m[i] - mn);
            m[i] = mn;
            float rs = 0.0f;
            #pragma unroll
            for (int j = 0; j < 4; j++) {
                s[i][j] = __expf(s[i][j] - mn);
                rs += s[i][j];
            }
            #pragma unroll
            for (int o = 8; o > 0; o >>= 1)
                rs += __shfl_xor_sync(0xffffffffu, rs, o);
            l[i] = l[i] * al + rs;
            #pragma unroll
            for (int j = 0; j < 4; j++) acc[i][j] *= al;
            float4 pv = make_float4(s[i][0], s[i][1], s[i][2], s[i][3]);
            *(float4*)&Ps[(ty * 4 + i) * 64 + tx * 4] = pv;
        }
        __syncthreads();

        for (int i = tid; i < 64 * 64; i += 256) {
            int r = i >> 6, c = i & 63;
            KVs[c * 65 + r] = base[(size_t)(kv0 + r) * (3 * EMB) + 2 * EMB + h * DHEAD + c];
        }
        __syncthreads();

        #pragma unroll 8
        for (int kk = 0; kk < 64; kk++) {
            float a[4], bb[4];
            #pragma unroll
            for (int i = 0; i < 4; i++) a[i]  = Ps[(ty * 4 + i) * 64 + kk];
            #pragma unroll
            for (int j = 0; j < 4; j++) bb[j] = KVs[(tx * 4 + j) * 65 + kk];
            #pragma unroll
            for (int i = 0; i < 4; i++)
                #pragma unroll
                for (int j = 0; j < 4; j++)
                    acc[i][j] = fmaf(a[i], bb[j], acc[i][j]);
        }
        __syncthreads();
    }

    #pragma unroll
    for (int i = 0; i < 4; i++) {
        float inv = 1.0f / l[i];
        float4 v = make_float4(acc[i][0] * inv, acc[i][1] * inv,
                               acc[i][2] * inv, acc[i][3] * inv);
        *(float4*)&outp[((size_t)(b * NTOK + q0 + ty * 4 + i)) * EMB + h * DHEAD + tx * 4] = v;
    }
}

// ---------------------------------------------------------------------------
extern "C" void kernel_launch(void* const* d_in, const int* in_sizes, int n_in,
                              void* d_out, int out_size)
{
    const float* x    = (const float*)d_in[0];   // (8,1024,1024)
    const float* Wqkv = (const float*)d_in[1];   // (3072,1024)
    const float* ab   = (const float*)d_in[2];   // (16,1024)
    const int*   bidx = (const int*)  d_in[3];   // (1024,1024)
    const float* Wout = (const float*)d_in[4];   // (1024,1024)
    const float* bout = (const float*)d_in[5];   // (1024,)
    float* out = (float*)d_out;

    float *qkv_p = nullptr, *att_p = nullptr;
    __nv_bfloat16 *xb, *wqkvb, *woutb, *attb;
    cudaGetSymbolAddress((void**)&qkv_p, g_qkv);
    cudaGetSymbolAddress((void**)&att_p, g_att);
    cudaGetSymbolAddress((void**)&xb, g_xb);
    cudaGetSymbolAddress((void**)&wqkvb, g_wqkvb);
    cudaGetSymbolAddress((void**)&woutb, g_woutb);
    cudaGetSymbolAddress((void**)&attb, g_attb);

    const int M = BATCH * NTOK;                 // 8192
    const size_t nx = (size_t)M * EMB;          // 8388608
    const size_t nw = (size_t)3 * EMB * EMB;    // 3145728
    const size_t no = (size_t)EMB * EMB;        // 1048576

    // 1) precision splits
    split_f32<<<(int)(nx / 4 / 256), 256>>>(x, xb, xb + nx, (int)nx);
    split_f32<<<(int)(nw / 4 / 256), 256>>>(Wqkv, wqkvb, wqkvb + nw, (int)nw);
    split_f32<<<(int)(no / 4 / 256), 256>>>(Wout, woutb, woutb + no, (int)no);

    const int GSMEM = 65536;
    cudaFuncSetAttribute(gemm_mma, cudaFuncAttributeMaxDynamicSharedMemorySize, GSMEM);

    // 2) QKV projection on tensor cores (mma.sync)
    gemm_mma<<<dim3(3 * EMB / 128, M / 128), 256, GSMEM>>>(
        xb, wqkvb, nullptr, qkv_p, M, 3 * EMB, 0);

    // 3) attention (fp32)
    const int ASMEM = (64 * 64 + 64 * 65 + 64 * 64 + 1024) * (int)sizeof(float);
    cudaFuncSetAttribute(attn_kernel, cudaFuncAttributeMaxDynamicSharedMemorySize, ASMEM);
    attn_kernel<<<dim3(NTOK / 64, HEADS, BATCH), 256, ASMEM>>>(ab, bidx, att_p);

    // 4) split attention output, output projection on tensor cores
    split_f32<<<(int)(nx / 4 / 256), 256>>>(att_p, attb, attb + nx, (int)nx);
    gemm_mma<<<dim3(EMB / 128, M / 128), 256, GSMEM>>>(
        attb, woutb, bout, out, M, EMB, 1);
}

// round 5
// speedup vs baseline: 2.5356x; 1.6655x over previous
#include <cuda_runtime.h>
#include <cuda_bf16.h>
#include <cstdint>
#include <math.h>

#define BATCH 8
#define NTOK  1024
#define EMB   1024
#define HEADS 16
#define DHEAD 64
#define ATT_SCALE 0.125f
#define GK 1024

// ---------------------------------------------------------------------------
// Scratch (device globals)
// ---------------------------------------------------------------------------
__device__ __nv_bfloat16 g_xb   [2 * (size_t)BATCH * NTOK * EMB];     // x hi|lo
__device__ __nv_bfloat16 g_wqkvb[2 * (size_t)3 * EMB * EMB];          // Wqkv hi|lo
__device__ __nv_bfloat16 g_woutb[2 * (size_t)EMB * EMB];              // Wout hi|lo
__device__ __nv_bfloat16 g_qkvb [2 * (size_t)BATCH * NTOK * 3 * EMB]; // qkv hi|lo
__device__ __nv_bfloat16 g_attb [2 * (size_t)BATCH * NTOK * EMB];     // att hi|lo

// ---------------------------------------------------------------------------
// helpers
// ---------------------------------------------------------------------------
__device__ __forceinline__ uint32_t smem_to_u32(const void* p) {
    uint32_t a;
    asm("{ .reg .u64 t; cvta.to.shared.u64 t, %1; cvt.u32.u64 %0, t; }"
        : "=r"(a) : "l"(p));
    return a;
}
#define SMEM_SWIZZLE_128B(o) ((o) ^ (((o) >> 3) & 0x70))

__device__ __forceinline__ void cp_async16(uint32_t saddr, const void* gaddr) {
    asm volatile("cp.async.cg.shared.global [%0], [%1], 16;"
                 :: "r"(saddr), "l"(gaddr));
}
__device__ __forceinline__ void cp_async_commit() {
    asm volatile("cp.async.commit_group;");
}
template<int N>
__device__ __forceinline__ void cp_async_wait() {
    asm volatile("cp.async.wait_group %0;" :: "n"(N));
}
__device__ __forceinline__ void ldmatrix_x4(uint32_t* r, uint32_t addr) {
    asm volatile("ldmatrix.sync.aligned.m8n8.x4.shared.b16 {%0,%1,%2,%3}, [%4];"
                 : "=r"(r[0]), "=r"(r[1]), "=r"(r[2]), "=r"(r[3]) : "r"(addr));
}
__device__ __forceinline__ void ldmatrix_x4_trans(uint32_t* r, uint32_t addr) {
    asm volatile("ldmatrix.sync.aligned.m8n8.x4.trans.shared.b16 {%0,%1,%2,%3}, [%4];"
                 : "=r"(r[0]), "=r"(r[1]), "=r"(r[2]), "=r"(r[3]) : "r"(addr));
}
__device__ __forceinline__ void mma16816(float* c, const uint32_t* a,
                                         uint32_t b0, uint32_t b1) {
    asm volatile("mma.sync.aligned.m16n8k16.row.col.f32.bf16.bf16.f32 "
                 "{%0,%1,%2,%3}, {%4,%5,%6,%7}, {%8,%9}, {%0,%1,%2,%3};"
                 : "+f"(c[0]), "+f"(c[1]), "+f"(c[2]), "+f"(c[3])
                 : "r"(a[0]), "r"(a[1]), "r"(a[2]), "r"(a[3]), "r"(b0), "r"(b1));
}
__device__ __forceinline__ uint32_t packh(__nv_bfloat16 a, __nv_bfloat16 b) {
    __nv_bfloat162 t; t.x = a; t.y = b;
    return *(uint32_t*)&t;     // a -> low 16 bits (first element)
}

// ---------------------------------------------------------------------------
// fp32 -> (bf16 hi, bf16 lo)
// ---------------------------------------------------------------------------
__global__ __launch_bounds__(256)
void split_f32(const float* __restrict__ s, __nv_bfloat16* __restrict__ hi,
               __nv_bfloat16* __restrict__ lo, int n)
{
    int i = (blockIdx.x * 256 + threadIdx.x) * 4;
    if (i >= n) return;
    float4 v = *(const float4*)(s + i);
    __nv_bfloat16 h0 = __float2bfloat16(v.x);
    __nv_bfloat16 h1 = __float2bfloat16(v.y);
    __nv_bfloat16 h2 = __float2bfloat16(v.z);
    __nv_bfloat16 h3 = __float2bfloat16(v.w);
    __nv_bfloat16 l0 = __float2bfloat16(v.x - __bfloat162float(h0));
    __nv_bfloat16 l1 = __float2bfloat16(v.y - __bfloat162float(h1));
    __nv_bfloat16 l2 = __float2bfloat16(v.z - __bfloat162float(h2));
    __nv_bfloat16 l3 = __float2bfloat16(v.w - __bfloat162float(h3));
    __nv_bfloat162 a = {h0, h1}, b = {h2, h3}, c = {l0, l1}, d = {l2, l3};
    *(__nv_bfloat162*)(hi + i)     = a;
    *(__nv_bfloat162*)(hi + i + 2) = b;
    *(__nv_bfloat162*)(lo + i)     = c;
    *(__nv_bfloat162*)(lo + i + 2) = d;
}

// ---------------------------------------------------------------------------
// mma.sync bf16x3 GEMM-NT.  writeSplit=0: C=f32 (+bias). writeSplit=1:
// C written as bf16 hi (Cb) + lo (Cb + M*N).
// ---------------------------------------------------------------------------
__global__ __launch_bounds__(256)
void gemm_mma(const __nv_bfloat16* __restrict__ A, const __nv_bfloat16* __restrict__ B,
              const float* __restrict__ bias, float* __restrict__ Cf,
              __nv_bfloat16* __restrict__ Cb,
              int M, int N, int addBias, int writeSplit)
{
    extern __shared__ char smem[];
    uint32_t sb = smem_to_u32(smem);

    int tid  = threadIdx.x;
    int wid  = tid >> 5, lane = tid & 31;
    int wm   = (wid >> 2) * 64;
    int wn   = (wid & 3) * 32;
    int row0 = blockIdx.y * 128, col0 = blockIdx.x * 128;

    float acc[4][4][4];
    #pragma unroll
    for (int i = 0; i < 4; i++)
        #pragma unroll
        for (int j = 0; j < 4; j++)
            #pragma unroll
            for (int k = 0; k < 4; k++) acc[i][j][k] = 0.0f;

    const int NCHUNKS = 48;
    int lr = tid >> 1;
    int lc = (tid & 1) << 2;

    auto load_chunk = [&](int ci, int buf) {
        int seg = ci >> 4;
        int k0  = (ci & 15) << 6;
        const __nv_bfloat16* Ag = A + (seg == 1 ? (size_t)M * GK : 0)
                                    + (size_t)row0 * GK + k0;
        const __nv_bfloat16* Bg = B + (seg == 2 ? (size_t)N * GK : 0)
                                    + (size_t)col0 * GK + k0;
        uint32_t abase = sb + buf * 16384;
        uint32_t bbase = sb + 32768 + buf * 16384;
        #pragma unroll
        for (int c = 0; c < 4; c++) {
            uint32_t off = (uint32_t)lr * 128 + (lc + c) * 16;
            uint32_t sw  = SMEM_SWIZZLE_128B(off);
            cp_async16(abase + sw, Ag + (size_t)lr * GK + (lc + c) * 8);
            cp_async16(bbase + sw, Bg + (size_t)lr * GK + (lc + c) * 8);
        }
        cp_async_commit();
    };

    load_chunk(0, 0);
    cp_async_wait<0>();
    __syncthreads();

    int mat = lane >> 3, ri = lane & 7;

    for (int ci = 0; ci < NCHUNKS; ci++) {
        int buf = ci & 1;
        if (ci + 1 < NCHUNKS) load_chunk(ci + 1, buf ^ 1);

        uint32_t abase = sb + buf * 16384;
        uint32_t bbase = sb + 32768 + buf * 16384;

        #pragma unroll
        for (int ks = 0; ks < 4; ks++) {
            uint32_t af[4][4];
            #pragma unroll
            for (int mi = 0; mi < 4; mi++) {
                int row = wm + mi * 16 + (mat & 1) * 8 + ri;
                int kb  = (ks * 16 + (mat >> 1) * 8) * 2;
                ldmatrix_x4(af[mi], abase + SMEM_SWIZZLE_128B((uint32_t)(row * 128 + kb)));
            }
            uint32_t bf[2][4];
            #pragma unroll
            for (int ni = 0; ni < 2; ni++) {
                int n  = wn + ni * 16 + (mat >> 1) * 8 + ri;
                int kb = (ks * 16 + (mat & 1) * 8) * 2;
                ldmatrix_x4(bf[ni], bbase + SMEM_SWIZZLE_128B((uint32_t)(n * 128 + kb)));
            }
            #pragma unroll
            for (int mi = 0; mi < 4; mi++)
                #pragma unroll
                for (int j = 0; j < 4; j++) {
                    int ni = j >> 1, pr = (j & 1) * 2;
                    mma16816(acc[mi][j], af[mi], bf[ni][pr], bf[ni][pr + 1]);
                }
        }
        cp_async_wait<0>();
        __syncthreads();
    }

    int tr = lane >> 2, tc = (lane & 3) * 2;
    __nv_bfloat16* Clo = Cb + (size_t)M * N;
    #pragma unroll
    for (int mi = 0; mi < 4; mi++) {
        #pragma unroll
        for (int j = 0; j < 4; j++) {
            int col = col0 + wn + j * 8 + tc;
            size_t rlo = (size_t)(row0 + wm + mi * 16 + tr) * N + col;
            size_t rhi = rlo + (size_t)8 * N;
            if (writeSplit) {
                #pragma unroll
                for (int half = 0; half < 2; half++) {
                    float va = acc[mi][j][half * 2], vb = acc[mi][j][half * 2 + 1];
                    size_t idx = half ? rhi : rlo;
                    __nv_bfloat16 ha = __float2bfloat16(va);
                    __nv_bfloat16 hb = __float2bfloat16(vb);
                    __nv_bfloat162 hv; hv.x = ha; hv.y = hb;
                    *(__nv_bfloat162*)(Cb + idx) = hv;
                    __nv_bfloat162 lv;
                    lv.x = __float2bfloat16(va - __bfloat162float(ha));
                    lv.y = __float2bfloat16(vb - __bfloat162float(hb));
                    *(__nv_bfloat162*)(Clo + idx) = lv;
                }
            } else {
                float bx = 0.f, by = 0.f;
                if (addBias) { bx = bias[col]; by = bias[col + 1]; }
                float2 v0 = make_float2(acc[mi][j][0] + bx, acc[mi][j][1] + by);
                float2 v1 = make_float2(acc[mi][j][2] + bx, acc[mi][j][3] + by);
                *(float2*)(Cf + rlo) = v0;
                *(float2*)(Cf + rhi) = v1;
            }
        }
    }
}

// ---------------------------------------------------------------------------
// Tensor-core flash attention (bf16x3 split).
// CTA = (128 q-rows, head, batch). 8 warps x 16 q-rows. KV tiles of 64.
// ---------------------------------------------------------------------------
__global__ __launch_bounds__(256)
void attn_mma(const __nv_bfloat16* __restrict__ qkvb,
              const float* __restrict__ biases,
              const int*   __restrict__ bidx,
              __nv_bfloat16* __restrict__ attb)
{
    extern __shared__ char smem[];
    uint32_t sb = smem_to_u32(smem);
    const uint32_t BUF0 = 4096, BUFSZ = 32768;
    const size_t LOQ = (size_t)BATCH * NTOK * 3 * EMB;

    int tid = threadIdx.x, wid = tid >> 5, lane = tid & 31;
    int q0 = blockIdx.x * 128, h = blockIdx.y, b = blockIdx.z;
    int wq = wid * 16;

    float* bsp = (float*)smem;                 // per-head bias row [1024]
    for (int i = tid; i < 1024; i += 256) bsp[i] = biases[h * 1024 + i];

    const __nv_bfloat16* hibase = qkvb;
    const __nv_bfloat16* lobase = qkvb + LOQ;
    size_t qrow0 = (size_t)(b * NTOK + q0);

    // ---- stage Q (hi at BUF0, lo at BUF0+16K) + ldmatrix into regs ----
    #pragma unroll
    for (int i = 0; i < 4; i++) {
        int idx = tid + i * 256;
        int r = idx >> 3, c = idx & 7;
        uint32_t sw = SMEM_SWIZZLE_128B((uint32_t)(r * 128 + c * 16));
        size_t go = (qrow0 + r) * (3 * EMB) + h * DHEAD + c * 8;
        cp_async16(sb + BUF0 + sw,          hibase + go);
        cp_async16(sb + BUF0 + 16384 + sw,  lobase + go);
    }
    cp_async_commit();
    cp_async_wait<0>();
    __syncthreads();

    int mat = lane >> 3, ri = lane & 7;
    uint32_t qh[4][4], ql[4][4];
    #pragma unroll
    for (int ks = 0; ks < 4; ks++) {
        int row = wq + (mat & 1) * 8 + ri;
        int kb  = (ks * 16 + (mat >> 1) * 8) * 2;
        uint32_t sw = SMEM_SWIZZLE_128B((uint32_t)(row * 128 + kb));
        ldmatrix_x4(qh[ks], sb + BUF0 + sw);
        ldmatrix_x4(ql[ks], sb + BUF0 + 16384 + sw);
    }
    __syncthreads();

    float o[8][4];
    #pragma unroll
    for (int j = 0; j < 8; j++)
        #pragma unroll
        for (int e = 0; e < 4; e++) o[j][e] = 0.0f;
    float l0 = 0.f, l1 = 0.f, m0 = -1e30f, m1 = -1e30f;

    auto load_kv = [&](int t, int buf) {
        int kvr = t * 64;
        uint32_t dst = sb + BUF0 + buf * BUFSZ;
        #pragma unroll
        for (int i = 0; i < 2; i++) {
            int idx = tid + i * 256;
            int r = idx >> 3, c = idx & 7;
            uint32_t sw = SMEM_SWIZZLE_128B((uint32_t)(r * 128 + c * 16));
            size_t gro = (size_t)(b * NTOK + kvr + r) * (3 * EMB) + h * DHEAD + c * 8;
            cp_async16(dst + sw,          hibase + gro + EMB);       // K hi
            cp_async16(dst + 8192 + sw,   lobase + gro + EMB);       // K lo
            cp_async16(dst + 16384 + sw,  hibase + gro + 2 * EMB);   // V hi
            cp_async16(dst + 24576 + sw,  lobase + gro + 2 * EMB);   // V lo
        }
        cp_async_commit();
    };

    load_kv(0, 0);

    int r0 = lane >> 2, c0 = (lane & 3) * 2;
    const int* bidx0 = bidx + (size_t)(q0 + wq + r0) * NTOK;
    const int* bidx1 = bidx0 + 8 * NTOK;

    for (int t = 0; t < 16; t++) {
        int buf = t & 1;
        if (t < 15) { load_kv(t + 1, buf ^ 1); cp_async_wait<1>(); }
        else        { cp_async_wait<0>(); }
        __syncthreads();

        uint32_t kbh = sb + BUF0 + buf * BUFSZ;
        uint32_t kbl = kbh + 8192, vbh = kbh + 16384, vbl = kbh + 24576;

        // ---- S = Qhi*Khi + Qlo*Khi + Qhi*Klo ----
        float s[8][4];
        #pragma unroll
        for (int j = 0; j < 8; j++)
            #pragma unroll
            for (int e = 0; e < 4; e++) s[j][e] = 0.0f;

        #pragma unroll
        for (int ks = 0; ks < 4; ks++) {
            uint32_t kh4[4][4], kl4[4][4];
            #pragma unroll
            for (int np = 0; np < 4; np++) {
                int n  = np * 16 + (mat >> 1) * 8 + ri;
                int kb = (ks * 16 + (mat & 1) * 8) * 2;
                uint32_t sw = SMEM_SWIZZLE_128B((uint32_t)(n * 128 + kb));
                ldmatrix_x4(kh4[np], kbh + sw);
                ldmatrix_x4(kl4[np], kbl + sw);
            }
            #pragma unroll
            for (int j = 0; j < 8; j++) {
                int ni = j >> 1, pr = (j & 1) * 2;
                mma16816(s[j], qh[ks], kh4[ni][pr], kh4[ni][pr + 1]);
                mma16816(s[j], ql[ks], kh4[ni][pr], kh4[ni][pr + 1]);
                mma16816(s[j], qh[ks], kl4[ni][pr], kl4[ni][pr + 1]);
            }
        }

        // ---- scale + bias gather ----
        int kv0 = t * 64;
        #pragma unroll
        for (int j = 0; j < 8; j++) {
            int col = kv0 + j * 8 + c0;
            int2 i0 = *(const int2*)(bidx0 + col);
            int2 i1 = *(const int2*)(bidx1 + col);
            s[j][0] = fmaf(s[j][0], ATT_SCALE, bsp[i0.x]);
            s[j][1] = fmaf(s[j][1], ATT_SCALE, bsp[i0.y]);
            s[j][2] = fmaf(s[j][2], ATT_SCALE, bsp[i1.x]);
            s[j][3] = fmaf(s[j][3], ATT_SCALE, bsp[i1.y]);
        }

        // ---- online softmax (rows r0, r0+8) ----
        float nm0 = -1e30f, nm1 = -1e30f;
        #pragma unroll
        for (int j = 0; j < 8; j++) {
            nm0 = fmaxf(nm0, fmaxf(s[j][0], s[j][1]));
            nm1 = fmaxf(nm1, fmaxf(s[j][2], s[j][3]));
        }
        nm0 = fmaxf(nm0, __shfl_xor_sync(0xffffffffu, nm0, 1));
        nm0 = fmaxf(nm0, __shfl_xor_sync(0xffffffffu, nm0, 2));
        nm1 = fmaxf(nm1, __shfl_xor_sync(0xffffffffu, nm1, 1));
        nm1 = fmaxf(nm1, __shfl_xor_sync(0xffffffffu, nm1, 2));
        nm0 = fmaxf(nm0, m0); nm1 = fmaxf(nm1, m1);
        float a0 = __expf(m0 - nm0), a1 = __expf(m1 - nm1);
        m0 = nm0; m1 = nm1;

        float sum0 = 0.f, sum1 = 0.f;
        #pragma unroll
        for (int j = 0; j < 8; j++) {
            s[j][0] = __expf(s[j][0] - nm0);
            s[j][1] = __expf(s[j][1] - nm0);
            s[j][2] = __expf(s[j][2] - nm1);
            s[j][3] = __expf(s[j][3] - nm1);
            sum0 += s[j][0] + s[j][1];
            sum1 += s[j][2] + s[j][3];
        }
        sum0 += __shfl_xor_sync(0xffffffffu, sum0, 1);
        sum0 += __shfl_xor_sync(0xffffffffu, sum0, 2);
        sum1 += __shfl_xor_sync(0xffffffffu, sum1, 1);
        sum1 += __shfl_xor_sync(0xffffffffu, sum1, 2);
        l0 = l0 * a0 + sum0;
        l1 = l1 * a1 + sum1;
        #pragma unroll
        for (int j = 0; j < 8; j++) {
            o[j][0] *= a0; o[j][1] *= a0;
            o[j][2] *= a1; o[j][3] *= a1;
        }

        // ---- O += Phi*Vhi + Plo*Vhi + Phi*Vlo ----
        #pragma unroll
        for (int ks = 0; ks < 4; ks++) {
            uint32_t ahi[4], alo[4];
            #pragma unroll
            for (int u = 0; u < 4; u++) {
                const float* P = s[2 * ks + (u >> 1)];
                float va = P[(u & 1) * 2], vb = P[(u & 1) * 2 + 1];
                __nv_bfloat16 ha = __float2bfloat16(va);
                __nv_bfloat16 hb = __float2bfloat16(vb);
                ahi[u] = packh(ha, hb);
                alo[u] = packh(__float2bfloat16(va - __bfloat162float(ha)),
                               __float2bfloat16(vb - __bfloat162float(hb)));
            }
            uint32_t vh4[4][4], vl4[4][4];
            #pragma unroll
            for (int np = 0; np < 4; np++) {
                int row = ks * 16 + (mat & 1) * 8 + ri;
                int cb  = (np * 16 + (mat >> 1) * 8) * 2;
                uint32_t sw = SMEM_SWIZZLE_128B((uint32_t)(row * 128 + cb));
                ldmatrix_x4_trans(vh4[np], vbh + sw);
                ldmatrix_x4_trans(vl4[np], vbl + sw);
            }
            #pragma unroll
            for (int j2 = 0; j2 < 8; j2++) {
                int ni = j2 >> 1, pr = (j2 & 1) * 2;
                mma16816(o[j2], ahi, vh4[ni][pr], vh4[ni][pr + 1]);
                mma16816(o[j2], alo, vh4[ni][pr], vh4[ni][pr + 1]);
                mma16816(o[j2], ahi, vl4[ni][pr], vl4[ni][pr + 1]);
            }
        }
        __syncthreads();
    }

    // ---- epilogue: normalize, split to bf16 hi/lo ----
    float inv0 = 1.0f / l0, inv1 = 1.0f / l1;
    __nv_bfloat16* ohi = attb;
    __nv_bfloat16* olo = attb + (size_t)BATCH * NTOK * EMB;
    size_t rowA = (qrow0 + wq + r0) * EMB;
    size_t rowB = rowA + (size_t)8 * EMB;
    #pragma unroll
    for (int j = 0; j < 8; j++) {
        int col = h * DHEAD + j * 8 + c0;
        float v0 = o[j][0] * inv0, v1 = o[j][1] * inv0;
        float v2 = o[j][2] * inv1, v3 = o[j][3] * inv1;
        __nv_bfloat16 h0 = __float2bfloat16(v0), h1 = __float2bfloat16(v1);
        __nv_bfloat16 h2 = __float2bfloat16(v2), h3 = __float2bfloat16(v3);
        __nv_bfloat162 hv0; hv0.x = h0; hv0.y = h1;
        __nv_bfloat162 hv1; hv1.x = h2; hv1.y = h3;
        *(__nv_bfloat162*)(ohi + rowA + col) = hv0;
        *(__nv_bfloat162*)(ohi + rowB + col) = hv1;
        __nv_bfloat162 lv0, lv1;
        lv0.x = __float2bfloat16(v0 - __bfloat162float(h0));
        lv0.y = __float2bfloat16(v1 - __bfloat162float(h1));
        lv1.x = __float2bfloat16(v2 - __bfloat162float(h2));
        lv1.y = __float2bfloat16(v3 - __bfloat162float(h3));
        *(__nv_bfloat162*)(olo + rowA + col) = lv0;
        *(__nv_bfloat162*)(olo + rowB + col) = lv1;
    }
}

// ---------------------------------------------------------------------------
extern "C" void kernel_launch(void* const* d_in, const int* in_sizes, int n_in,
                              void* d_out, int out_size)
{
    const float* x    = (const float*)d_in[0];
    const float* Wqkv = (const float*)d_in[1];
    const float* ab   = (const float*)d_in[2];
    const int*   bidx = (const int*)  d_in[3];
    const float* Wout = (const float*)d_in[4];
    const float* bout = (const float*)d_in[5];
    float* out = (float*)d_out;

    __nv_bfloat16 *xb, *wqkvb, *woutb, *qkvb, *attb;
    cudaGetSymbolAddress((void**)&xb, g_xb);
    cudaGetSymbolAddress((void**)&wqkvb, g_wqkvb);
    cudaGetSymbolAddress((void**)&woutb, g_woutb);
    cudaGetSymbolAddress((void**)&qkvb, g_qkvb);
    cudaGetSymbolAddress((void**)&attb, g_attb);

    const int M = BATCH * NTOK;
    const size_t nx = (size_t)M * EMB;
    const size_t nw = (size_t)3 * EMB * EMB;
    const size_t no = (size_t)EMB * EMB;

    split_f32<<<(int)(nx / 4 / 256), 256>>>(x, xb, xb + nx, (int)nx);
    split_f32<<<(int)(nw / 4 / 256), 256>>>(Wqkv, wqkvb, wqkvb + nw, (int)nw);
    split_f32<<<(int)(no / 4 / 256), 256>>>(Wout, woutb, woutb + no, (int)no);

    const int GSMEM = 65536;
    cudaFuncSetAttribute(gemm_mma, cudaFuncAttributeMaxDynamicSharedMemorySize, GSMEM);

    // QKV projection -> bf16 hi/lo directly
    gemm_mma<<<dim3(3 * EMB / 128, M / 128), 256, GSMEM>>>(
        xb, wqkvb, nullptr, nullptr, qkvb, M, 3 * EMB, 0, 1);

    // tensor-core attention -> bf16 hi/lo
    const int ASMEM = 4096 + 2 * 32768;   // 69632
    cudaFuncSetAttribute(attn_mma, cudaFuncAttributeMaxDynamicSharedMemorySize, ASMEM);
    attn_mma<<<dim3(NTOK / 128, HEADS, BATCH), 256, ASMEM>>>(qkvb, ab, bidx, attb);

    // output projection (f32 + bias)
    gemm_mma<<<dim3(EMB / 128, M / 128), 256, GSMEM>>>(
        attb, woutb, bout, out, nullptr, M, EMB, 1, 0);
}

// round 6
// speedup vs baseline: 3.3514x; 1.3217x over previous
#include <cuda_runtime.h>
#include <cuda_fp16.h>
#include <cstdint>
#include <math.h>

#define BATCH 8
#define NTOK  1024
#define EMB   1024
#define HEADS 16
#define DHEAD 64
#define ATT_SCALE 0.125f
#define GK 1024

// ---------------------------------------------------------------------------
// Scratch (device globals)
// ---------------------------------------------------------------------------
__device__ __half g_xh   [2 * (size_t)BATCH * NTOK * EMB];     // x hi|lo
__device__ __half g_wqkvh[(size_t)3 * EMB * EMB];              // Wqkv fp16
__device__ __half g_wouth[(size_t)EMB * EMB];                  // Wout fp16
__device__ __half g_qkvh [2 * (size_t)BATCH * NTOK * 3 * EMB]; // qkv hi|lo
__device__ __half g_atth [2 * (size_t)BATCH * NTOK * EMB];     // att hi|lo

// ---------------------------------------------------------------------------
// helpers
// ---------------------------------------------------------------------------
__device__ __forceinline__ uint32_t smem_to_u32(const void* p) {
    uint32_t a;
    asm("{ .reg .u64 t; cvta.to.shared.u64 t, %1; cvt.u32.u64 %0, t; }"
        : "=r"(a) : "l"(p));
    return a;
}
#define SMEM_SWIZZLE_128B(o) ((o) ^ (((o) >> 3) & 0x70))

__device__ __forceinline__ void cp_async16(uint32_t saddr, const void* gaddr) {
    asm volatile("cp.async.cg.shared.global [%0], [%1], 16;"
                 :: "r"(saddr), "l"(gaddr));
}
__device__ __forceinline__ void cp_async_commit() {
    asm volatile("cp.async.commit_group;");
}
template<int N>
__device__ __forceinline__ void cp_async_wait() {
    asm volatile("cp.async.wait_group %0;" :: "n"(N));
}
__device__ __forceinline__ void ldmatrix_x4(uint32_t* r, uint32_t addr) {
    asm volatile("ldmatrix.sync.aligned.m8n8.x4.shared.b16 {%0,%1,%2,%3}, [%4];"
                 : "=r"(r[0]), "=r"(r[1]), "=r"(r[2]), "=r"(r[3]) : "r"(addr));
}
__device__ __forceinline__ void ldmatrix_x4_trans(uint32_t* r, uint32_t addr) {
    asm volatile("ldmatrix.sync.aligned.m8n8.x4.trans.shared.b16 {%0,%1,%2,%3}, [%4];"
                 : "=r"(r[0]), "=r"(r[1]), "=r"(r[2]), "=r"(r[3]) : "r"(addr));
}
__device__ __forceinline__ void mma16816(float* c, const uint32_t* a,
                                         uint32_t b0, uint32_t b1) {
    asm volatile("mma.sync.aligned.m16n8k16.row.col.f32.f16.f16.f32 "
                 "{%0,%1,%2,%3}, {%4,%5,%6,%7}, {%8,%9}, {%0,%1,%2,%3};"
                 : "+f"(c[0]), "+f"(c[1]), "+f"(c[2]), "+f"(c[3])
                 : "r"(a[0]), "r"(a[1]), "r"(a[2]), "r"(a[3]), "r"(b0), "r"(b1));
}
__device__ __forceinline__ uint32_t packh(__half a, __half b) {
    __half2 t; t.x = a; t.y = b;
    return *(uint32_t*)&t;
}

// ---------------------------------------------------------------------------
// conversions
// ---------------------------------------------------------------------------
__global__ __launch_bounds__(256)
void split_f32h(const float* __restrict__ s, __half* __restrict__ hi,
                __half* __restrict__ lo, int n)
{
    int i = (blockIdx.x * 256 + threadIdx.x) * 4;
    if (i >= n) return;
    float4 v = *(const float4*)(s + i);
    __half h0 = __float2half_rn(v.x), h1 = __float2half_rn(v.y);
    __half h2 = __float2half_rn(v.z), h3 = __float2half_rn(v.w);
    __half2 a; a.x = h0; a.y = h1;
    __half2 b; b.x = h2; b.y = h3;
    *(__half2*)(hi + i)     = a;
    *(__half2*)(hi + i + 2) = b;
    __half2 c, d;
    c.x = __float2half_rn(v.x - __half2float(h0));
    c.y = __float2half_rn(v.y - __half2float(h1));
    d.x = __float2half_rn(v.z - __half2float(h2));
    d.y = __float2half_rn(v.w - __half2float(h3));
    *(__half2*)(lo + i)     = c;
    *(__half2*)(lo + i + 2) = d;
}

__global__ __launch_bounds__(256)
void cvt_f32h(const float* __restrict__ s, __half* __restrict__ d, int n)
{
    int i = (blockIdx.x * 256 + threadIdx.x) * 4;
    if (i >= n) return;
    float4 v = *(const float4*)(s + i);
    __half2 a; a.x = __float2half_rn(v.x); a.y = __float2half_rn(v.y);
    __half2 b; b.x = __float2half_rn(v.z); b.y = __float2half_rn(v.w);
    *(__half2*)(d + i)     = a;
    *(__half2*)(d + i + 2) = b;
}

// ---------------------------------------------------------------------------
// fp16x2 GEMM-NT: C[M,N] = (A_hi + A_lo)[M,GK] * B[N,GK]^T (+bias)
// A split hi|lo (lo at +M*GK); B plain fp16. Tile 128x128, BK=64.
// Per chunk: A_hi/A_lo/B tiles share one stage (48KB), double buffered.
// ---------------------------------------------------------------------------
__global__ __launch_bounds__(256, 2)
void gemm_mma(const __half* __restrict__ A, const __half* __restrict__ B,
              const float* __restrict__ bias, float* __restrict__ Cf,
              __half* __restrict__ Cb,
              int M, int N, int addBias, int writeSplit)
{
    extern __shared__ char smem[];
    uint32_t sb = smem_to_u32(smem);

    int tid  = threadIdx.x;
    int wid  = tid >> 5, lane = tid & 31;
    int wm   = (wid >> 2) * 64;
    int wn   = (wid & 3) * 32;
    int row0 = blockIdx.y * 128, col0 = blockIdx.x * 128;

    float acc[4][4][4];
    #pragma unroll
    for (int i = 0; i < 4; i++)
        #pragma unroll
        for (int j = 0; j < 4; j++)
            #pragma unroll
            for (int k = 0; k < 4; k++) acc[i][j][k] = 0.0f;

    const int NCHUNKS = 16;
    int lr = tid >> 1;
    int lc = (tid & 1) << 2;

    auto load_chunk = [&](int ci, int buf) {
        int k0 = ci << 6;
        const __half* Ah = A + (size_t)row0 * GK + k0;
        const __half* Al = Ah + (size_t)M * GK;
        const __half* Bg = B + (size_t)col0 * GK + k0;
        uint32_t base = sb + buf * 49152;
        #pragma unroll
        for (int c = 0; c < 4; c++) {
            uint32_t off = (uint32_t)lr * 128 + (lc + c) * 16;
            uint32_t sw  = SMEM_SWIZZLE_128B(off);
            size_t go = (size_t)lr * GK + (lc + c) * 8;
            cp_async16(base + sw,          Ah + go);
            cp_async16(base + 16384 + sw,  Al + go);
            cp_async16(base + 32768 + sw,  Bg + go);
        }
        cp_async_commit();
    };

    load_chunk(0, 0);
    cp_async_wait<0>();
    __syncthreads();

    int mat = lane >> 3, ri = lane & 7;

    for (int ci = 0; ci < NCHUNKS; ci++) {
        int buf = ci & 1;
        if (ci + 1 < NCHUNKS) load_chunk(ci + 1, buf ^ 1);

        uint32_t abase = sb + buf * 49152;
        uint32_t bbase = abase + 32768;

        #pragma unroll
        for (int ks = 0; ks < 4; ks++) {
            uint32_t ah[4][4], al[4][4];
            #pragma unroll
            for (int mi = 0; mi < 4; mi++) {
                int row = wm + mi * 16 + (mat & 1) * 8 + ri;
                int kb  = (ks * 16 + (mat >> 1) * 8) * 2;
                uint32_t sw = SMEM_SWIZZLE_128B((uint32_t)(row * 128 + kb));
                ldmatrix_x4(ah[mi], abase + sw);
                ldmatrix_x4(al[mi], abase + 16384 + sw);
            }
            uint32_t bfr[2][4];
            #pragma unroll
            for (int ni = 0; ni < 2; ni++) {
                int n  = wn + ni * 16 + (mat >> 1) * 8 + ri;
                int kb = (ks * 16 + (mat & 1) * 8) * 2;
                ldmatrix_x4(bfr[ni], bbase + SMEM_SWIZZLE_128B((uint32_t)(n * 128 + kb)));
            }
            #pragma unroll
            for (int mi = 0; mi < 4; mi++)
                #pragma unroll
                for (int j = 0; j < 4; j++) {
                    int ni = j >> 1, pr = (j & 1) * 2;
                    mma16816(acc[mi][j], ah[mi], bfr[ni][pr], bfr[ni][pr + 1]);
                    mma16816(acc[mi][j], al[mi], bfr[ni][pr], bfr[ni][pr + 1]);
                }
        }
        cp_async_wait<0>();
        __syncthreads();
    }

    int tr = lane >> 2, tc = (lane & 3) * 2;
    __half* Clo = Cb + (size_t)M * N;
    #pragma unroll
    for (int mi = 0; mi < 4; mi++) {
        #pragma unroll
        for (int j = 0; j < 4; j++) {
            int col = col0 + wn + j * 8 + tc;
            size_t rlo = (size_t)(row0 + wm + mi * 16 + tr) * N + col;
            size_t rhi = rlo + (size_t)8 * N;
            if (writeSplit) {
                #pragma unroll
                for (int half_i = 0; half_i < 2; half_i++) {
                    float va = acc[mi][j][half_i * 2], vb = acc[mi][j][half_i * 2 + 1];
                    size_t idx = half_i ? rhi : rlo;
                    __half ha = __float2half_rn(va);
                    __half hb = __float2half_rn(vb);
                    __half2 hv; hv.x = ha; hv.y = hb;
                    *(__half2*)(Cb + idx) = hv;
                    __half2 lv;
                    lv.x = __float2half_rn(va - __half2float(ha));
                    lv.y = __float2half_rn(vb - __half2float(hb));
                    *(__half2*)(Clo + idx) = lv;
                }
            } else {
                float bx = 0.f, by = 0.f;
                if (addBias) { bx = bias[col]; by = bias[col + 1]; }
                float2 v0 = make_float2(acc[mi][j][0] + bx, acc[mi][j][1] + by);
                float2 v1 = make_float2(acc[mi][j][2] + bx, acc[mi][j][3] + by);
                *(float2*)(Cf + rlo) = v0;
                *(float2*)(Cf + rhi) = v1;
            }
        }
    }
}

// ---------------------------------------------------------------------------
// Tensor-core flash attention, fp16x2.
// Q = hi+lo split (exact); K, V plain fp16 (hi buffer only).
// CTA = (128 q-rows, head, batch). 8 warps x 16 q-rows. KV tiles of 64.
// ---------------------------------------------------------------------------
__global__ __launch_bounds__(256)
void attn_mma(const __half* __restrict__ qkvh,
              const float* __restrict__ biases,
              const int*   __restrict__ bidx,
              __half* __restrict__ atth)
{
    extern __shared__ char smem[];
    uint32_t sb = smem_to_u32(smem);
    const uint32_t BUF0 = 4096, BUFSZ = 16384;
    const size_t LOQ = (size_t)BATCH * NTOK * 3 * EMB;

    int tid = threadIdx.x, wid = tid >> 5, lane = tid & 31;
    int q0 = blockIdx.x * 128, h = blockIdx.y, bz = blockIdx.z;
    int wq = wid * 16;

    float* bsp = (float*)smem;                 // per-head bias row [1024]
    for (int i = tid; i < 1024; i += 256) bsp[i] = biases[h * 1024 + i];

    const __half* hibase = qkvh;
    const __half* lobase = qkvh + LOQ;
    size_t qrow0 = (size_t)(bz * NTOK + q0);

    // ---- stage Q hi/lo, extract fragments ----
    #pragma unroll
    for (int i = 0; i < 4; i++) {
        int idx = tid + i * 256;
        int r = idx >> 3, c = idx & 7;
        uint32_t sw = SMEM_SWIZZLE_128B((uint32_t)(r * 128 + c * 16));
        size_t go = (qrow0 + r) * (3 * EMB) + h * DHEAD + c * 8;
        cp_async16(sb + BUF0 + sw,          hibase + go);
        cp_async16(sb + BUF0 + 16384 + sw,  lobase + go);
    }
    cp_async_commit();
    cp_async_wait<0>();
    __syncthreads();

    int mat = lane >> 3, ri = lane & 7;
    uint32_t qh[4][4], ql[4][4];
    #pragma unroll
    for (int ks = 0; ks < 4; ks++) {
        int row = wq + (mat & 1) * 8 + ri;
        int kb  = (ks * 16 + (mat >> 1) * 8) * 2;
        uint32_t sw = SMEM_SWIZZLE_128B((uint32_t)(row * 128 + kb));
        ldmatrix_x4(qh[ks], sb + BUF0 + sw);
        ldmatrix_x4(ql[ks], sb + BUF0 + 16384 + sw);
    }
    __syncthreads();

    float o[8][4];
    #pragma unroll
    for (int j = 0; j < 8; j++)
        #pragma unroll
        for (int e = 0; e < 4; e++) o[j][e] = 0.0f;
    float l0 = 0.f, l1 = 0.f, m0 = -1e30f, m1 = -1e30f;

    auto load_kv = [&](int t, int buf) {
        int kvr = t * 64;
        uint32_t dst = sb + BUF0 + buf * BUFSZ;
        #pragma unroll
        for (int i = 0; i < 2; i++) {
            int idx = tid + i * 256;
            int r = idx >> 3, c = idx & 7;
            uint32_t sw = SMEM_SWIZZLE_128B((uint32_t)(r * 128 + c * 16));
            size_t gro = (size_t)(bz * NTOK + kvr + r) * (3 * EMB) + h * DHEAD + c * 8;
            cp_async16(dst + sw,         hibase + gro + EMB);       // K fp16
            cp_async16(dst + 8192 + sw,  hibase + gro + 2 * EMB);   // V fp16
        }
        cp_async_commit();
    };

    load_kv(0, 0);

    int r0 = lane >> 2, c0 = (lane & 3) * 2;
    const int* bidx0 = bidx + (size_t)(q0 + wq + r0) * NTOK;
    const int* bidx1 = bidx0 + 8 * NTOK;

    for (int t = 0; t < 16; t++) {
        int buf = t & 1;
        if (t < 15) { load_kv(t + 1, buf ^ 1); cp_async_wait<1>(); }
        else        { cp_async_wait<0>(); }
        __syncthreads();

        uint32_t kbh = sb + BUF0 + buf * BUFSZ;
        uint32_t vbh = kbh + 8192;

        // ---- S = (Qhi + Qlo) * K ----
        float s[8][4];
        #pragma unroll
        for (int j = 0; j < 8; j++)
            #pragma unroll
            for (int e = 0; e < 4; e++) s[j][e] = 0.0f;

        #pragma unroll
        for (int ks = 0; ks < 4; ks++) {
            uint32_t kh4[4][4];
            #pragma unroll
            for (int np = 0; np < 4; np++) {
                int n  = np * 16 + (mat >> 1) * 8 + ri;
                int kb = (ks * 16 + (mat & 1) * 8) * 2;
                ldmatrix_x4(kh4[np], kbh + SMEM_SWIZZLE_128B((uint32_t)(n * 128 + kb)));
            }
            #pragma unroll
            for (int j = 0; j < 8; j++) {
                int ni = j >> 1, pr = (j & 1) * 2;
                mma16816(s[j], qh[ks], kh4[ni][pr], kh4[ni][pr + 1]);
                mma16816(s[j], ql[ks], kh4[ni][pr], kh4[ni][pr + 1]);
            }
        }

        // ---- scale + bias gather ----
        int kv0 = t * 64;
        #pragma unroll
        for (int j = 0; j < 8; j++) {
            int col = kv0 + j * 8 + c0;
            int2 i0 = *(const int2*)(bidx0 + col);
            int2 i1 = *(const int2*)(bidx1 + col);
            s[j][0] = fmaf(s[j][0], ATT_SCALE, bsp[i0.x]);
            s[j][1] = fmaf(s[j][1], ATT_SCALE, bsp[i0.y]);
            s[j][2] = fmaf(s[j][2], ATT_SCALE, bsp[i1.x]);
            s[j][3] = fmaf(s[j][3], ATT_SCALE, bsp[i1.y]);
        }

        // ---- online softmax (rows r0, r0+8) ----
        float nm0 = -1e30f, nm1 = -1e30f;
        #pragma unroll
        for (int j = 0; j < 8; j++) {
            nm0 = fmaxf(nm0, fmaxf(s[j][0], s[j][1]));
            nm1 = fmaxf(nm1, fmaxf(s[j][2], s[j][3]));
        }
        nm0 = fmaxf(nm0, __shfl_xor_sync(0xffffffffu, nm0, 1));
        nm0 = fmaxf(nm0, __shfl_xor_sync(0xffffffffu, nm0, 2));
        nm1 = fmaxf(nm1, __shfl_xor_sync(0xffffffffu, nm1, 1));
        nm1 = fmaxf(nm1, __shfl_xor_sync(0xffffffffu, nm1, 2));
        nm0 = fmaxf(nm0, m0); nm1 = fmaxf(nm1, m1);
        float a0 = __expf(m0 - nm0), a1 = __expf(m1 - nm1);
        m0 = nm0; m1 = nm1;

        float sum0 = 0.f, sum1 = 0.f;
        #pragma unroll
        for (int j = 0; j < 8; j++) {
            s[j][0] = __expf(s[j][0] - nm0);
            s[j][1] = __expf(s[j][1] - nm0);
            s[j][2] = __expf(s[j][2] - nm1);
            s[j][3] = __expf(s[j][3] - nm1);
            sum0 += s[j][0] + s[j][1];
            sum1 += s[j][2] + s[j][3];
        }
        sum0 += __shfl_xor_sync(0xffffffffu, sum0, 1);
        sum0 += __shfl_xor_sync(0xffffffffu, sum0, 2);
        sum1 += __shfl_xor_sync(0xffffffffu, sum1, 1);
        sum1 += __shfl_xor_sync(0xffffffffu, sum1, 2);
        l0 = l0 * a0 + sum0;
        l1 = l1 * a1 + sum1;
        #pragma unroll
        for (int j = 0; j < 8; j++) {
            o[j][0] *= a0; o[j][1] *= a0;
            o[j][2] *= a1; o[j][3] *= a1;
        }

        // ---- O += (Phi + Plo) * V ----
        #pragma unroll
        for (int ks = 0; ks < 4; ks++) {
            uint32_t phi[4], plo[4];
            #pragma unroll
            for (int u = 0; u < 4; u++) {
                const float* P = s[2 * ks + (u >> 1)];
                float va = P[(u & 1) * 2], vb = P[(u & 1) * 2 + 1];
                __half ha = __float2half_rn(va);
                __half hb = __float2half_rn(vb);
                phi[u] = packh(ha, hb);
                plo[u] = packh(__float2half_rn(va - __half2float(ha)),
                               __float2half_rn(vb - __half2float(hb)));
            }
            uint32_t vh4[4][4];
            #pragma unroll
            for (int np = 0; np < 4; np++) {
                int row = ks * 16 + (mat & 1) * 8 + ri;
                int cb  = (np * 16 + (mat >> 1) * 8) * 2;
                ldmatrix_x4_trans(vh4[np], vbh + SMEM_SWIZZLE_128B((uint32_t)(row * 128 + cb)));
            }
            #pragma unroll
            for (int j2 = 0; j2 < 8; j2++) {
                int ni = j2 >> 1, pr = (j2 & 1) * 2;
                mma16816(o[j2], phi, vh4[ni][pr], vh4[ni][pr + 1]);
                mma16816(o[j2], plo, vh4[ni][pr], vh4[ni][pr + 1]);
            }
        }
        __syncthreads();
    }

    // ---- epilogue: normalize, split to fp16 hi/lo ----
    float inv0 = 1.0f / l0, inv1 = 1.0f / l1;
    __half* ohi = atth;
    __half* olo = atth + (size_t)BATCH * NTOK * EMB;
    size_t rowA = (qrow0 + wq + r0) * EMB;
    size_t rowB = rowA + (size_t)8 * EMB;
    #pragma unroll
    for (int j = 0; j < 8; j++) {
        int col = h * DHEAD + j * 8 + c0;
        float v0 = o[j][0] * inv0, v1 = o[j][1] * inv0;
        float v2 = o[j][2] * inv1, v3 = o[j][3] * inv1;
        __half h0 = __float2half_rn(v0), h1 = __float2half_rn(v1);
        __half h2 = __float2half_rn(v2), h3 = __float2half_rn(v3);
        __half2 hv0; hv0.x = h0; hv0.y = h1;
        __half2 hv1; hv1.x = h2; hv1.y = h3;
        *(__half2*)(ohi + rowA + col) = hv0;
        *(__half2*)(ohi + rowB + col) = hv1;
        __half2 lv0, lv1;
        lv0.x = __float2half_rn(v0 - __half2float(h0));
        lv0.y = __float2half_rn(v1 - __half2float(h1));
        lv1.x = __float2half_rn(v2 - __half2float(h2));
        lv1.y = __float2half_rn(v3 - __half2float(h3));
        *(__half2*)(olo + rowA + col) = lv0;
        *(__half2*)(olo + rowB + col) = lv1;
    }
}

// ---------------------------------------------------------------------------
extern "C" void kernel_launch(void* const* d_in, const int* in_sizes, int n_in,
                              void* d_out, int out_size)
{
    const float* x    = (const float*)d_in[0];
    const float* Wqkv = (const float*)d_in[1];
    const float* ab   = (const float*)d_in[2];
    const int*   bidx = (const int*)  d_in[3];
    const float* Wout = (const float*)d_in[4];
    const float* bout = (const float*)d_in[5];
    float* out = (float*)d_out;

    __half *xh, *wqkvh, *wouth, *qkvh, *atth;
    cudaGetSymbolAddress((void**)&xh, g_xh);
    cudaGetSymbolAddress((void**)&wqkvh, g_wqkvh);
    cudaGetSymbolAddress((void**)&wouth, g_wouth);
    cudaGetSymbolAddress((void**)&qkvh, g_qkvh);
    cudaGetSymbolAddress((void**)&atth, g_atth);

    const int M = BATCH * NTOK;
    const size_t nx = (size_t)M * EMB;
    const size_t nw = (size_t)3 * EMB * EMB;
    const size_t no = (size_t)EMB * EMB;

    split_f32h<<<(int)(nx / 4 / 256), 256>>>(x, xh, xh + nx, (int)nx);
    cvt_f32h<<<(int)(nw / 4 / 256), 256>>>(Wqkv, wqkvh, (int)nw);
    cvt_f32h<<<(int)(no / 4 / 256), 256>>>(Wout, wouth, (int)no);

    const int GSMEM = 98304;   // 2 x (16K A_hi + 16K A_lo + 16K B)
    cudaFuncSetAttribute(gemm_mma, cudaFuncAttributeMaxDynamicSharedMemorySize, GSMEM);

    // QKV projection -> fp16 hi/lo
    gemm_mma<<<dim3(3 * EMB / 128, M / 128), 256, GSMEM>>>(
        xh, wqkvh, nullptr, nullptr, qkvh, M, 3 * EMB, 0, 1);

    // attention -> fp16 hi/lo
    const int ASMEM = 4096 + 32768;   // 36864
    cudaFuncSetAttribute(attn_mma, cudaFuncAttributeMaxDynamicSharedMemorySize, ASMEM);
    attn_mma<<<dim3(NTOK / 128, HEADS, BATCH), 256, ASMEM>>>(qkvh, ab, bidx, atth);

    // output projection (f32 + bias)
    gemm_mma<<<dim3(EMB / 128, M / 128), 256, GSMEM>>>(
        atth, wouth, bout, out, nullptr, M, EMB, 1, 0);
}

// round 9
// speedup vs baseline: 5.8934x; 1.7585x over previous
#include <cuda_runtime.h>
#include <cuda_fp16.h>
#include <cstdint>
#include <math.h>

#define BATCH 8
#define NTOK  1024
#define EMB   1024
#define HEADS 16
#define DHEAD 64
#define ATT_SCALE 0.125f
#define GK 1024

// ---------------------------------------------------------------------------
// Scratch (device globals)
// ---------------------------------------------------------------------------
__device__ __half g_xh   [(size_t)BATCH * NTOK * EMB];
__device__ __half g_wqkvh[(size_t)3 * EMB * EMB];
__device__ __half g_wouth[(size_t)EMB * EMB];
__device__ __half g_qkvh [(size_t)BATCH * NTOK * 3 * EMB];
__device__ __half g_atth [(size_t)BATCH * NTOK * EMB];

// ---------------------------------------------------------------------------
// helpers
// ---------------------------------------------------------------------------
__device__ __forceinline__ uint32_t smem_to_u32(const void* p) {
    uint32_t a;
    asm("{ .reg .u64 t; cvta.to.shared.u64 t, %1; cvt.u32.u64 %0, t; }"
        : "=r"(a) : "l"(p));
    return a;
}
#define SMEM_SWIZZLE_128B(o) ((o) ^ (((o) >> 3) & 0x70))

__device__ __forceinline__ void cp_async16(uint32_t saddr, const void* gaddr) {
    asm volatile("cp.async.cg.shared.global [%0], [%1], 16;"
                 :: "r"(saddr), "l"(gaddr));
}
__device__ __forceinline__ void cp_async_commit() {
    asm volatile("cp.async.commit_group;");
}
template<int N>
__device__ __forceinline__ void cp_async_wait() {
    asm volatile("cp.async.wait_group %0;" :: "n"(N));
}
__device__ __forceinline__ void ldmatrix_x4(uint32_t* r, uint32_t addr) {
    asm volatile("ldmatrix.sync.aligned.m8n8.x4.shared.b16 {%0,%1,%2,%3}, [%4];"
                 : "=r"(r[0]), "=r"(r[1]), "=r"(r[2]), "=r"(r[3]) : "r"(addr));
}
__device__ __forceinline__ void ldmatrix_x4_trans(uint32_t* r, uint32_t addr) {
    asm volatile("ldmatrix.sync.aligned.m8n8.x4.trans.shared.b16 {%0,%1,%2,%3}, [%4];"
                 : "=r"(r[0]), "=r"(r[1]), "=r"(r[2]), "=r"(r[3]) : "r"(addr));
}
__device__ __forceinline__ void mma16816(float* c, const uint32_t* a,
                                         uint32_t b0, uint32_t b1) {
    asm volatile("mma.sync.aligned.m16n8k16.row.col.f32.f16.f16.f32 "
                 "{%0,%1,%2,%3}, {%4,%5,%6,%7}, {%8,%9}, {%0,%1,%2,%3};"
                 : "+f"(c[0]), "+f"(c[1]), "+f"(c[2]), "+f"(c[3])
                 : "r"(a[0]), "r"(a[1]), "r"(a[2]), "r"(a[3]), "r"(b0), "r"(b1));
}
__device__ __forceinline__ uint32_t packh(__half a, __half b) {
    __half2 t; t.x = a; t.y = b;
    return *(uint32_t*)&t;
}

// ---------------------------------------------------------------------------
// fp32 -> fp16 conversion
// ---------------------------------------------------------------------------
__global__ __launch_bounds__(256)
void cvt_f32h(const float* __restrict__ s, __half* __restrict__ d, int n)
{
    int i = (blockIdx.x * 256 + threadIdx.x) * 4;
    if (i >= n) return;
    float4 v = *(const float4*)(s + i);
    __half2 a; a.x = __float2half_rn(v.x); a.y = __float2half_rn(v.y);
    __half2 b; b.x = __float2half_rn(v.z); b.y = __float2half_rn(v.w);
    *(__half2*)(d + i)     = a;
    *(__half2*)(d + i + 2) = b;
}

// ---------------------------------------------------------------------------
// fp16 GEMM-NT: C[M,N] = A[M,GK] * B[N,GK]^T (+bias)
// Tile 128x128, BK=64, 2-stage 32KB ring -> 2 CTAs/SM.
// writeSplit=1: C -> fp16 (Cb); else f32 (+bias).
// ---------------------------------------------------------------------------
__global__ __launch_bounds__(256, 2)
void gemm_mma(const __half* __restrict__ A, const __half* __restrict__ B,
              const float* __restrict__ bias, float* __restrict__ Cf,
              __half* __restrict__ Cb,
              int M, int N, int addBias, int writeSplit)
{
    extern __shared__ char smem[];
    uint32_t sb = smem_to_u32(smem);

    int tid  = threadIdx.x;
    int wid  = tid >> 5, lane = tid & 31;
    int wm   = (wid >> 2) * 64;
    int wn   = (wid & 3) * 32;
    int row0 = blockIdx.y * 128, col0 = blockIdx.x * 128;

    float acc[4][4][4];
    #pragma unroll
    for (int i = 0; i < 4; i++)
        #pragma unroll
        for (int j = 0; j < 4; j++)
            #pragma unroll
            for (int k = 0; k < 4; k++) acc[i][j][k] = 0.0f;

    const int NCHUNKS = 16;
    int lr = tid >> 1;
    int lc = (tid & 1) << 2;

    auto load_chunk = [&](int ci, int buf) {
        int k0 = ci << 6;
        const __half* Ag = A + (size_t)row0 * GK + k0;
        const __half* Bg = B + (size_t)col0 * GK + k0;
        uint32_t base = sb + buf * 32768;
        #pragma unroll
        for (int c = 0; c < 4; c++) {
            uint32_t off = (uint32_t)lr * 128 + (lc + c) * 16;
            uint32_t sw  = SMEM_SWIZZLE_128B(off);
            size_t go = (size_t)lr * GK + (lc + c) * 8;
            cp_async16(base + sw,          Ag + go);
            cp_async16(base + 16384 + sw,  Bg + go);
        }
        cp_async_commit();
    };

    load_chunk(0, 0);
    cp_async_wait<0>();
    __syncthreads();

    int mat = lane >> 3, ri = lane & 7;

    for (int ci = 0; ci < NCHUNKS; ci++) {
        int buf = ci & 1;
        if (ci + 1 < NCHUNKS) load_chunk(ci + 1, buf ^ 1);

        uint32_t abase = sb + buf * 32768;
        uint32_t bbase = abase + 16384;

        #pragma unroll
        for (int ks = 0; ks < 4; ks++) {
            uint32_t af[4][4];
            #pragma unroll
            for (int mi = 0; mi < 4; mi++) {
                int row = wm + mi * 16 + (mat & 1) * 8 + ri;
                int kb  = (ks * 16 + (mat >> 1) * 8) * 2;
                ldmatrix_x4(af[mi], abase + SMEM_SWIZZLE_128B((uint32_t)(row * 128 + kb)));
            }
            uint32_t bfr[2][4];
            #pragma unroll
            for (int ni = 0; ni < 2; ni++) {
                int n  = wn + ni * 16 + (mat >> 1) * 8 + ri;
                int kb = (ks * 16 + (mat & 1) * 8) * 2;
                ldmatrix_x4(bfr[ni], bbase + SMEM_SWIZZLE_128B((uint32_t)(n * 128 + kb)));
            }
            #pragma unroll
            for (int mi = 0; mi < 4; mi++)
                #pragma unroll
                for (int j = 0; j < 4; j++) {
                    int ni = j >> 1, pr = (j & 1) * 2;
                    mma16816(acc[mi][j], af[mi], bfr[ni][pr], bfr[ni][pr + 1]);
                }
        }
        cp_async_wait<0>();
        __syncthreads();
    }

    int tr = lane >> 2, tc = (lane & 3) * 2;
    #pragma unroll
    for (int mi = 0; mi < 4; mi++) {
        #pragma unroll
        for (int j = 0; j < 4; j++) {
            int col = col0 + wn + j * 8 + tc;
            size_t rlo = (size_t)(row0 + wm + mi * 16 + tr) * N + col;
            size_t rhi = rlo + (size_t)8 * N;
            if (writeSplit) {
                __half2 hv0, hv1;
                hv0.x = __float2half_rn(acc[mi][j][0]);
                hv0.y = __float2half_rn(acc[mi][j][1]);
                hv1.x = __float2half_rn(acc[mi][j][2]);
                hv1.y = __float2half_rn(acc[mi][j][3]);
                *(__half2*)(Cb + rlo) = hv0;
                *(__half2*)(Cb + rhi) = hv1;
            } else {
                float bx = 0.f, by = 0.f;
                if (addBias) { bx = bias[col]; by = bias[col + 1]; }
                float2 v0 = make_float2(acc[mi][j][0] + bx, acc[mi][j][1] + by);
                float2 v1 = make_float2(acc[mi][j][2] + bx, acc[mi][j][3] + by);
                *(float2*)(Cf + rlo) = v0;
                *(float2*)(Cf + rhi) = v1;
            }
        }
    }
}

// ---------------------------------------------------------------------------
// Tensor-core flash attention, pure fp16 operands, fp32 accum/softmax.
// CTA = (128 q-rows, head, batch). 8 warps x 16 q-rows. KV tiles of 64.
// ---------------------------------------------------------------------------
__global__ __launch_bounds__(256)
void attn_mma(const __half* __restrict__ qkvh,
              const float* __restrict__ biases,
              const int*   __restrict__ bidx,
              __half* __restrict__ atth)
{
    extern __shared__ char smem[];
    uint32_t sb = smem_to_u32(smem);
    const uint32_t BUF0 = 4096, BUFSZ = 16384;

    int tid = threadIdx.x, wid = tid >> 5, lane = tid & 31;
    int q0 = blockIdx.x * 128, h = blockIdx.y, bz = blockIdx.z;
    int wq = wid * 16;

    float* bsp = (float*)smem;                 // per-head bias row [1024]
    for (int i = tid; i < 1024; i += 256) bsp[i] = biases[h * 1024 + i];

    size_t qrow0 = (size_t)(bz * NTOK + q0);

    // ---- stage Q, extract fragments ----
    #pragma unroll
    for (int i = 0; i < 4; i++) {
        int idx = tid + i * 256;
        int r = idx >> 3, c = idx & 7;
        uint32_t sw = SMEM_SWIZZLE_128B((uint32_t)(r * 128 + c * 16));
        size_t go = (qrow0 + r) * (3 * EMB) + h * DHEAD + c * 8;
        cp_async16(sb + BUF0 + sw, qkvh + go);
    }
    cp_async_commit();
    cp_async_wait<0>();
    __syncthreads();

    int mat = lane >> 3, ri = lane & 7;
    uint32_t qh[4][4];
    #pragma unroll
    for (int ks = 0; ks < 4; ks++) {
        int row = wq + (mat & 1) * 8 + ri;
        int kb  = (ks * 16 + (mat >> 1) * 8) * 2;
        ldmatrix_x4(qh[ks], sb + BUF0 + SMEM_SWIZZLE_128B((uint32_t)(row * 128 + kb)));
    }
    __syncthreads();

    float o[8][4];
    #pragma unroll
    for (int j = 0; j < 8; j++)
        #pragma unroll
        for (int e = 0; e < 4; e++) o[j][e] = 0.0f;
    float l0 = 0.f, l1 = 0.f, m0 = -1e30f, m1 = -1e30f;

    auto load_kv = [&](int t, int buf) {
        int kvr = t * 64;
        uint32_t dst = sb + BUF0 + buf * BUFSZ;
        #pragma unroll
        for (int i = 0; i < 2; i++) {
            int idx = tid + i * 256;
            int r = idx >> 3, c = idx & 7;
            uint32_t sw = SMEM_SWIZZLE_128B((uint32_t)(r * 128 + c * 16));
            size_t gro = (size_t)(bz * NTOK + kvr + r) * (3 * EMB) + h * DHEAD + c * 8;
            cp_async16(dst + sw,        qkvh + gro + EMB);       // K
            cp_async16(dst + 8192 + sw, qkvh + gro + 2 * EMB);   // V
        }
        cp_async_commit();
    };

    load_kv(0, 0);

    int r0 = lane >> 2, c0 = (lane & 3) * 2;
    const int* bidx0 = bidx + (size_t)(q0 + wq + r0) * NTOK;
    const int* bidx1 = bidx0 + 8 * NTOK;

    for (int t = 0; t < 16; t++) {
        int buf = t & 1;
        if (t < 15) { load_kv(t + 1, buf ^ 1); cp_async_wait<1>(); }
        else        { cp_async_wait<0>(); }
        __syncthreads();

        uint32_t kbh = sb + BUF0 + buf * BUFSZ;
        uint32_t vbh = kbh + 8192;

        // ---- S = Q * K^T ----
        float s[8][4];
        #pragma unroll
        for (int j = 0; j < 8; j++)
            #pragma unroll
            for (int e = 0; e < 4; e++) s[j][e] = 0.0f;

        #pragma unroll
        for (int ks = 0; ks < 4; ks++) {
            uint32_t kh4[4][4];
            #pragma unroll
            for (int np = 0; np < 4; np++) {
                int n  = np * 16 + (mat >> 1) * 8 + ri;
                int kb = (ks * 16 + (mat & 1) * 8) * 2;
                ldmatrix_x4(kh4[np], kbh + SMEM_SWIZZLE_128B((uint32_t)(n * 128 + kb)));
            }
            #pragma unroll
            for (int j = 0; j < 8; j++) {
                int ni = j >> 1, pr = (j & 1) * 2;
                mma16816(s[j], qh[ks], kh4[ni][pr], kh4[ni][pr + 1]);
            }
        }

        // ---- scale + bias gather ----
        int kv0 = t * 64;
        #pragma unroll
        for (int j = 0; j < 8; j++) {
            int col = kv0 + j * 8 + c0;
            int2 i0 = *(const int2*)(bidx0 + col);
            int2 i1 = *(const int2*)(bidx1 + col);
            s[j][0] = fmaf(s[j][0], ATT_SCALE, bsp[i0.x]);
            s[j][1] = fmaf(s[j][1], ATT_SCALE, bsp[i0.y]);
            s[j][2] = fmaf(s[j][2], ATT_SCALE, bsp[i1.x]);
            s[j][3] = fmaf(s[j][3], ATT_SCALE, bsp[i1.y]);
        }

        // ---- online softmax (rows r0, r0+8) ----
        float nm0 = -1e30f, nm1 = -1e30f;
        #pragma unroll
        for (int j = 0; j < 8; j++) {
            nm0 = fmaxf(nm0, fmaxf(s[j][0], s[j][1]));
            nm1 = fmaxf(nm1, fmaxf(s[j][2], s[j][3]));
        }
        nm0 = fmaxf(nm0, __shfl_xor_sync(0xffffffffu, nm0, 1));
        nm0 = fmaxf(nm0, __shfl_xor_sync(0xffffffffu, nm0, 2));
        nm1 = fmaxf(nm1, __shfl_xor_sync(0xffffffffu, nm1, 1));
        nm1 = fmaxf(nm1, __shfl_xor_sync(0xffffffffu, nm1, 2));
        nm0 = fmaxf(nm0, m0); nm1 = fmaxf(nm1, m1);
        float a0 = __expf(m0 - nm0), a1 = __expf(m1 - nm1);
        m0 = nm0; m1 = nm1;

        float sum0 = 0.f, sum1 = 0.f;
        #pragma unroll
        for (int j = 0; j < 8; j++) {
            s[j][0] = __expf(s[j][0] - nm0);
            s[j][1] = __expf(s[j][1] - nm0);
            s[j][2] = __expf(s[j][2] - nm1);
            s[j][3] = __expf(s[j][3] - nm1);
            sum0 += s[j][0] + s[j][1];
            sum1 += s[j][2] + s[j][3];
        }
        sum0 += __shfl_xor_sync(0xffffffffu, sum0, 1);
        sum0 += __shfl_xor_sync(0xffffffffu, sum0, 2);
        sum1 += __shfl_xor_sync(0xffffffffu, sum1, 1);
        sum1 += __shfl_xor_sync(0xffffffffu, sum1, 2);
        l0 = l0 * a0 + sum0;
        l1 = l1 * a1 + sum1;
        #pragma unroll
        for (int j = 0; j < 8; j++) {
            o[j][0] *= a0; o[j][1] *= a0;
            o[j][2] *= a1; o[j][3] *= a1;
        }

        // ---- O += P * V ----
        #pragma unroll
        for (int ks = 0; ks < 4; ks++) {
            uint32_t phi[4];
            #pragma unroll
            for (int u = 0; u < 4; u++) {
                const float* P = s[2 * ks + (u >> 1)];
                phi[u] = packh(__float2half_rn(P[(u & 1) * 2]),
                               __float2half_rn(P[(u & 1) * 2 + 1]));
            }
            uint32_t vh4[4][4];
            #pragma unroll
            for (int np = 0; np < 4; np++) {
                int row = ks * 16 + (mat & 1) * 8 + ri;
                int cb  = (np * 16 + (mat >> 1) * 8) * 2;
                ldmatrix_x4_trans(vh4[np], vbh + SMEM_SWIZZLE_128B((uint32_t)(row * 128 + cb)));
            }
            #pragma unroll
            for (int j2 = 0; j2 < 8; j2++) {
                int ni = j2 >> 1, pr = (j2 & 1) * 2;
                mma16816(o[j2], phi, vh4[ni][pr], vh4[ni][pr + 1]);
            }
        }
        __syncthreads();
    }

    // ---- epilogue: normalize, write fp16 ----
    float inv0 = 1.0f / l0, inv1 = 1.0f / l1;
    size_t rowA = (qrow0 + wq + r0) * EMB;
    size_t rowB = rowA + (size_t)8 * EMB;
    #pragma unroll
    for (int j = 0; j < 8; j++) {
        int col = h * DHEAD + j * 8 + c0;
        __half2 hv0, hv1;
        hv0.x = __float2half_rn(o[j][0] * inv0);
        hv0.y = __float2half_rn(o[j][1] * inv0);
        hv1.x = __float2half_rn(o[j][2] * inv1);
        hv1.y = __float2half_rn(o[j][3] * inv1);
        *(__half2*)(atth + rowA + col) = hv0;
        *(__half2*)(atth + rowB + col) = hv1;
    }
}

// ---------------------------------------------------------------------------
extern "C" void kernel_launch(void* const* d_in, const int* in_sizes, int n_in,
                              void* d_out, int out_size)
{
    const float* x    = (const float*)d_in[0];
    const float* Wqkv = (const float*)d_in[1];
    const float* ab   = (const float*)d_in[2];
    const int*   bidx = (const int*)  d_in[3];
    const float* Wout = (const float*)d_in[4];
    const float* bout = (const float*)d_in[5];
    float* out = (float*)d_out;

    __half *xh, *wqkvh, *wouth, *qkvh, *atth;
    cudaGetSymbolAddress((void**)&xh, g_xh);
    cudaGetSymbolAddress((void**)&wqkvh, g_wqkvh);
    cudaGetSymbolAddress((void**)&wouth, g_wouth);
    cudaGetSymbolAddress((void**)&qkvh, g_qkvh);
    cudaGetSymbolAddress((void**)&atth, g_atth);

    const int M = BATCH * NTOK;
    const size_t nx = (size_t)M * EMB;
    const size_t nw = (size_t)3 * EMB * EMB;
    const size_t no = (size_t)EMB * EMB;

    cvt_f32h<<<(int)(nx / 4 / 256), 256>>>(x, xh, (int)nx);
    cvt_f32h<<<(int)(nw / 4 / 256), 256>>>(Wqkv, wqkvh, (int)nw);
    cvt_f32h<<<(int)(no / 4 / 256), 256>>>(Wout, wouth, (int)no);

    const int GSMEM = 65536;   // 2-stage x 32KB  -> 2 CTAs/SM
    cudaFuncSetAttribute(gemm_mma, cudaFuncAttributeMaxDynamicSharedMemorySize, GSMEM);

    // QKV projection -> fp16
    gemm_mma<<<dim3(3 * EMB / 128, M / 128), 256, GSMEM>>>(
        xh, wqkvh, nullptr, nullptr, qkvh, M, 3 * EMB, 0, 1);

    // attention -> fp16
    const int ASMEM = 4096 + 2 * 16384;   // 36864
    cudaFuncSetAttribute(attn_mma, cudaFuncAttributeMaxDynamicSharedMemorySize, ASMEM);
    attn_mma<<<dim3(NTOK / 128, HEADS, BATCH), 256, ASMEM>>>(qkvh, ab, bidx, atth);

    // output projection (f32 + bias)
    gemm_mma<<<dim3(EMB / 128, M / 128), 256, GSMEM>>>(
        atth, wouth, bout, out, nullptr, M, EMB, 1, 0);
}

// round 11
// speedup vs baseline: 6.5520x; 1.1118x over previous
#include <cuda_runtime.h>
#include <cuda_fp16.h>
#include <cstdint>
#include <math.h>

#define BATCH 8
#define NTOK  1024
#define EMB   1024
#define HEADS 16
#define DHEAD 64
#define ATT_SCALE 0.125f
#define GK 1024

// ---------------------------------------------------------------------------
// Scratch (device globals)
// ---------------------------------------------------------------------------
__device__ __half g_xh   [(size_t)BATCH * NTOK * EMB];
__device__ __half g_wqkvh[(size_t)3 * EMB * EMB];
__device__ __half g_wouth[(size_t)EMB * EMB];
__device__ __half g_qkvh [(size_t)BATCH * NTOK * 3 * EMB];
__device__ __half g_atth [(size_t)BATCH * NTOK * EMB];

// ---------------------------------------------------------------------------
// helpers
// ---------------------------------------------------------------------------
__device__ __forceinline__ uint32_t smem_to_u32(const void* p) {
    uint32_t a;
    asm("{ .reg .u64 t; cvta.to.shared.u64 t, %1; cvt.u32.u64 %0, t; }"
        : "=r"(a) : "l"(p));
    return a;
}
#define SMEM_SWIZZLE_128B(o) ((o) ^ (((o) >> 3) & 0x70))

__device__ __forceinline__ void cp_async16(uint32_t saddr, const void* gaddr) {
    asm volatile("cp.async.cg.shared.global [%0], [%1], 16;"
                 :: "r"(saddr), "l"(gaddr));
}
__device__ __forceinline__ void cp_async_commit() {
    asm volatile("cp.async.commit_group;");
}
template<int N>
__device__ __forceinline__ void cp_async_wait() {
    asm volatile("cp.async.wait_group %0;" :: "n"(N));
}
__device__ __forceinline__ void ldmatrix_x4(uint32_t* r, uint32_t addr) {
    asm volatile("ldmatrix.sync.aligned.m8n8.x4.shared.b16 {%0,%1,%2,%3}, [%4];"
                 : "=r"(r[0]), "=r"(r[1]), "=r"(r[2]), "=r"(r[3]) : "r"(addr));
}
__device__ __forceinline__ void ldmatrix_x4_trans(uint32_t* r, uint32_t addr) {
    asm volatile("ldmatrix.sync.aligned.m8n8.x4.trans.shared.b16 {%0,%1,%2,%3}, [%4];"
                 : "=r"(r[0]), "=r"(r[1]), "=r"(r[2]), "=r"(r[3]) : "r"(addr));
}
__device__ __forceinline__ void mma16816(float* c, const uint32_t* a,
                                         uint32_t b0, uint32_t b1) {
    asm volatile("mma.sync.aligned.m16n8k16.row.col.f32.f16.f16.f32 "
                 "{%0,%1,%2,%3}, {%4,%5,%6,%7}, {%8,%9}, {%0,%1,%2,%3};"
                 : "+f"(c[0]), "+f"(c[1]), "+f"(c[2]), "+f"(c[3])
                 : "r"(a[0]), "r"(a[1]), "r"(a[2]), "r"(a[3]), "r"(b0), "r"(b1));
}
__device__ __forceinline__ uint32_t packh(__half a, __half b) {
    __half2 t; t.x = a; t.y = b;
    return *(uint32_t*)&t;
}

// ---------------------------------------------------------------------------
// fp32 -> fp16 conversion
// ---------------------------------------------------------------------------
__global__ __launch_bounds__(256)
void cvt_f32h(const float* __restrict__ s, __half* __restrict__ d, int n)
{
    int i = (blockIdx.x * 256 + threadIdx.x) * 4;
    if (i >= n) return;
    float4 v = *(const float4*)(s + i);
    __half2 a; a.x = __float2half_rn(v.x); a.y = __float2half_rn(v.y);
    __half2 b; b.x = __float2half_rn(v.z); b.y = __float2half_rn(v.w);
    *(__half2*)(d + i)     = a;
    *(__half2*)(d + i + 2) = b;
}

// ---------------------------------------------------------------------------
// fp16 GEMM-NT: C[M,N] = A[M,GK] * B[N,GK]^T (+bias)
// Tile 128x128, BK=64, 3-stage 32KB ring (96KB) -> 2 CTAs/SM.
// ---------------------------------------------------------------------------
__global__ __launch_bounds__(256, 2)
void gemm_mma(const __half* __restrict__ A, const __half* __restrict__ B,
              const float* __restrict__ bias, float* __restrict__ Cf,
              __half* __restrict__ Cb,
              int M, int N, int addBias, int writeSplit)
{
    extern __shared__ char smem[];
    uint32_t sb = smem_to_u32(smem);

    int tid  = threadIdx.x;
    int wid  = tid >> 5, lane = tid & 31;
    int wm   = (wid >> 2) * 64;
    int wn   = (wid & 3) * 32;
    int row0 = blockIdx.y * 128, col0 = blockIdx.x * 128;

    float acc[4][4][4];
    #pragma unroll
    for (int i = 0; i < 4; i++)
        #pragma unroll
        for (int j = 0; j < 4; j++)
            #pragma unroll
            for (int k = 0; k < 4; k++) acc[i][j][k] = 0.0f;

    const int NCHUNKS = 16;
    int lr = tid >> 1;
    int lc = (tid & 1) << 2;

    auto load_chunk = [&](int ci, int slot) {
        int k0 = ci << 6;
        const __half* Ag = A + (size_t)row0 * GK + k0;
        const __half* Bg = B + (size_t)col0 * GK + k0;
        uint32_t base = sb + slot * 32768;
        #pragma unroll
        for (int c = 0; c < 4; c++) {
            uint32_t off = (uint32_t)lr * 128 + (lc + c) * 16;
            uint32_t sw  = SMEM_SWIZZLE_128B(off);
            size_t go = (size_t)lr * GK + (lc + c) * 8;
            cp_async16(base + sw,          Ag + go);
            cp_async16(base + 16384 + sw,  Bg + go);
        }
        cp_async_commit();
    };

    load_chunk(0, 0);
    load_chunk(1, 1);
    cp_async_wait<1>();
    __syncthreads();

    int mat = lane >> 3, ri = lane & 7;

    int buf = 0, nslot = 2;
    for (int ci = 0; ci < NCHUNKS; ci++) {
        if (ci + 2 < NCHUNKS) {
            load_chunk(ci + 2, nslot);
            nslot = (nslot == 2) ? 0 : nslot + 1;
        }

        uint32_t abase = sb + buf * 32768;
        uint32_t bbase = abase + 16384;

        #pragma unroll
        for (int ks = 0; ks < 4; ks++) {
            uint32_t af[4][4];
            #pragma unroll
            for (int mi = 0; mi < 4; mi++) {
                int row = wm + mi * 16 + (mat & 1) * 8 + ri;
                int kb  = (ks * 16 + (mat >> 1) * 8) * 2;
                ldmatrix_x4(af[mi], abase + SMEM_SWIZZLE_128B((uint32_t)(row * 128 + kb)));
            }
            uint32_t bfr[2][4];
            #pragma unroll
            for (int ni = 0; ni < 2; ni++) {
                int n  = wn + ni * 16 + (mat >> 1) * 8 + ri;
                int kb = (ks * 16 + (mat & 1) * 8) * 2;
                ldmatrix_x4(bfr[ni], bbase + SMEM_SWIZZLE_128B((uint32_t)(n * 128 + kb)));
            }
            #pragma unroll
            for (int mi = 0; mi < 4; mi++)
                #pragma unroll
                for (int j = 0; j < 4; j++) {
                    int ni = j >> 1, pr = (j & 1) * 2;
                    mma16816(acc[mi][j], af[mi], bfr[ni][pr], bfr[ni][pr + 1]);
                }
        }
        if (ci + 2 < NCHUNKS)      cp_async_wait<1>();
        else                       cp_async_wait<0>();
        __syncthreads();
        buf = (buf == 2) ? 0 : buf + 1;
    }

    int tr = lane >> 2, tc = (lane & 3) * 2;
    #pragma unroll
    for (int mi = 0; mi < 4; mi++) {
        #pragma unroll
        for (int j = 0; j < 4; j++) {
            int col = col0 + wn + j * 8 + tc;
            size_t rlo = (size_t)(row0 + wm + mi * 16 + tr) * N + col;
            size_t rhi = rlo + (size_t)8 * N;
            if (writeSplit) {
                __half2 hv0, hv1;
                hv0.x = __float2half_rn(acc[mi][j][0]);
                hv0.y = __float2half_rn(acc[mi][j][1]);
                hv1.x = __float2half_rn(acc[mi][j][2]);
                hv1.y = __float2half_rn(acc[mi][j][3]);
                *(__half2*)(Cb + rlo) = hv0;
                *(__half2*)(Cb + rhi) = hv1;
            } else {
                float bx = 0.f, by = 0.f;
                if (addBias) { bx = bias[col]; by = bias[col + 1]; }
                float2 v0 = make_float2(acc[mi][j][0] + bx, acc[mi][j][1] + by);
                float2 v1 = make_float2(acc[mi][j][2] + bx, acc[mi][j][3] + by);
                *(float2*)(Cf + rlo) = v0;
                *(float2*)(Cf + rhi) = v1;
            }
        }
    }
}

// ---------------------------------------------------------------------------
// Tensor-core flash attention, fp16 operands, fp32 accum/softmax.
// Bias index computed ANALYTICALLY: idx = |r1-r2|*32 + |c1-c2| (RES=32 grid).
// 3-stage KV ring. CTA = (128 q-rows, head, batch); 8 warps x 16 q-rows.
// ---------------------------------------------------------------------------
__global__ __launch_bounds__(256, 2)
void attn_mma(const __half* __restrict__ qkvh,
              const float* __restrict__ biases,
              __half* __restrict__ atth)
{
    extern __shared__ char smem[];
    uint32_t sb = smem_to_u32(smem);
    const uint32_t BUF0 = 4096, SLOT = 16384;

    int tid = threadIdx.x, wid = tid >> 5, lane = tid & 31;
    int q0 = blockIdx.x * 128, h = blockIdx.y, bz = blockIdx.z;
    int wq = wid * 16;

    float* bsp = (float*)smem;                 // per-head bias row [1024]
    for (int i = tid; i < 1024; i += 256) bsp[i] = biases[h * 1024 + i];

    size_t qrow0 = (size_t)(bz * NTOK + q0);

    // ---- stage Q in slot 0, extract fragments ----
    #pragma unroll
    for (int i = 0; i < 4; i++) {
        int idx = tid + i * 256;
        int r = idx >> 3, c = idx & 7;
        uint32_t sw = SMEM_SWIZZLE_128B((uint32_t)(r * 128 + c * 16));
        size_t go = (qrow0 + r) * (3 * EMB) + h * DHEAD + c * 8;
        cp_async16(sb + BUF0 + sw, qkvh + go);
    }
    cp_async_commit();
    cp_async_wait<0>();
    __syncthreads();

    int mat = lane >> 3, ri = lane & 7;
    uint32_t qh[4][4];
    #pragma unroll
    for (int ks = 0; ks < 4; ks++) {
        int row = wq + (mat & 1) * 8 + ri;
        int kb  = (ks * 16 + (mat >> 1) * 8) * 2;
        ldmatrix_x4(qh[ks], sb + BUF0 + SMEM_SWIZZLE_128B((uint32_t)(row * 128 + kb)));
    }
    __syncthreads();

    float o[8][4];
    #pragma unroll
    for (int j = 0; j < 8; j++)
        #pragma unroll
        for (int e = 0; e < 4; e++) o[j][e] = 0.0f;
    float l0 = 0.f, l1 = 0.f, m0 = -1e30f, m1 = -1e30f;

    auto load_kv = [&](int t, int slot) {
        int kvr = t * 64;
        uint32_t dst = sb + BUF0 + slot * SLOT;
        #pragma unroll
        for (int i = 0; i < 2; i++) {
            int idx = tid + i * 256;
            int r = idx >> 3, c = idx & 7;
            uint32_t sw = SMEM_SWIZZLE_128B((uint32_t)(r * 128 + c * 16));
            size_t gro = (size_t)(bz * NTOK + kvr + r) * (3 * EMB) + h * DHEAD + c * 8;
            cp_async16(dst + sw,        qkvh + gro + EMB);       // K
            cp_async16(dst + 8192 + sw, qkvh + gro + 2 * EMB);   // V
        }
        cp_async_commit();
    };

    load_kv(0, 0);
    load_kv(1, 1);
    cp_async_wait<1>();
    __syncthreads();

    int r0 = lane >> 2, c0 = (lane & 3) * 2;
    // analytic bias geometry for this thread's two q rows
    int gi0 = q0 + wq + r0, gi1 = gi0 + 8;
    int qr0 = gi0 >> 5, qc0 = gi0 & 31;
    int qr1 = gi1 >> 5, qc1 = gi1 & 31;

    int buf = 0, nslot = 2;
    for (int t = 0; t < 16; t++) {
        if (t + 2 < 16) {
            load_kv(t + 2, nslot);
            nslot = (nslot == 2) ? 0 : nslot + 1;
        }

        uint32_t kbh = sb + BUF0 + buf * SLOT;
        uint32_t vbh = kbh + 8192;

        // ---- S = Q * K^T ----
        float s[8][4];
        #pragma unroll
        for (int j = 0; j < 8; j++)
            #pragma unroll
            for (int e = 0; e < 4; e++) s[j][e] = 0.0f;

        #pragma unroll
        for (int ks = 0; ks < 4; ks++) {
            uint32_t kh4[4][4];
            #pragma unroll
            for (int np = 0; np < 4; np++) {
                int n  = np * 16 + (mat >> 1) * 8 + ri;
                int kb = (ks * 16 + (mat & 1) * 8) * 2;
                ldmatrix_x4(kh4[np], kbh + SMEM_SWIZZLE_128B((uint32_t)(n * 128 + kb)));
            }
            #pragma unroll
            for (int j = 0; j < 8; j++) {
                int ni = j >> 1, pr = (j & 1) * 2;
                mma16816(s[j], qh[ks], kh4[ni][pr], kh4[ni][pr + 1]);
            }
        }

        // ---- scale + analytic bias ----
        int kv0 = t * 64;
        #pragma unroll
        for (int j = 0; j < 8; j++) {
            int cA = kv0 + j * 8 + c0;
            int cB = cA + 1;
            int krA = cA >> 5, kcA = cA & 31;
            int krB = cB >> 5, kcB = cB & 31;
            s[j][0] = fmaf(s[j][0], ATT_SCALE, bsp[abs(qr0 - krA) * 32 + abs(qc0 - kcA)]);
            s[j][1] = fmaf(s[j][1], ATT_SCALE, bsp[abs(qr0 - krB) * 32 + abs(qc0 - kcB)]);
            s[j][2] = fmaf(s[j][2], ATT_SCALE, bsp[abs(qr1 - krA) * 32 + abs(qc1 - kcA)]);
            s[j][3] = fmaf(s[j][3], ATT_SCALE, bsp[abs(qr1 - krB) * 32 + abs(qc1 - kcB)]);
        }

        // ---- online softmax (rows r0, r0+8) ----
        float nm0 = -1e30f, nm1 = -1e30f;
        #pragma unroll
        for (int j = 0; j < 8; j++) {
            nm0 = fmaxf(nm0, fmaxf(s[j][0], s[j][1]));
            nm1 = fmaxf(nm1, fmaxf(s[j][2], s[j][3]));
        }
        nm0 = fmaxf(nm0, __shfl_xor_sync(0xffffffffu, nm0, 1));
        nm0 = fmaxf(nm0, __shfl_xor_sync(0xffffffffu, nm0, 2));
        nm1 = fmaxf(nm1, __shfl_xor_sync(0xffffffffu, nm1, 1));
        nm1 = fmaxf(nm1, __shfl_xor_sync(0xffffffffu, nm1, 2));
        nm0 = fmaxf(nm0, m0); nm1 = fmaxf(nm1, m1);
        float a0 = __expf(m0 - nm0), a1 = __expf(m1 - nm1);
        m0 = nm0; m1 = nm1;

        float sum0 = 0.f, sum1 = 0.f;
        #pragma unroll
        for (int j = 0; j < 8; j++) {
            s[j][0] = __expf(s[j][0] - nm0);
            s[j][1] = __expf(s[j][1] - nm0);
            s[j][2] = __expf(s[j][2] - nm1);
            s[j][3] = __expf(s[j][3] - nm1);
            sum0 += s[j][0] + s[j][1];
            sum1 += s[j][2] + s[j][3];
        }
        sum0 += __shfl_xor_sync(0xffffffffu, sum0, 1);
        sum0 += __shfl_xor_sync(0xffffffffu, sum0, 2);
        sum1 += __shfl_xor_sync(0xffffffffu, sum1, 1);
        sum1 += __shfl_xor_sync(0xffffffffu, sum1, 2);
        l0 = l0 * a0 + sum0;
        l1 = l1 * a1 + sum1;
        #pragma unroll
        for (int j = 0; j < 8; j++) {
            o[j][0] *= a0; o[j][1] *= a0;
            o[j][2] *= a1; o[j][3] *= a1;
        }

        // ---- O += P * V ----
        #pragma unroll
        for (int ks = 0; ks < 4; ks++) {
            uint32_t phi[4];
            #pragma unroll
            for (int u = 0; u < 4; u++) {
                const float* P = s[2 * ks + (u >> 1)];
                phi[u] = packh(__float2half_rn(P[(u & 1) * 2]),
                               __float2half_rn(P[(u & 1) * 2 + 1]));
            }
            uint32_t vh4[4][4];
            #pragma unroll
            for (int np = 0; np < 4; np++) {
                int row = ks * 16 + (mat & 1) * 8 + ri;
                int cb  = (np * 16 + (mat >> 1) * 8) * 2;
                ldmatrix_x4_trans(vh4[np], vbh + SMEM_SWIZZLE_128B((uint32_t)(row * 128 + cb)));
            }
            #pragma unroll
            for (int j2 = 0; j2 < 8; j2++) {
                int ni = j2 >> 1, pr = (j2 & 1) * 2;
                mma16816(o[j2], phi, vh4[ni][pr], vh4[ni][pr + 1]);
            }
        }
        if (t + 2 < 16)      cp_async_wait<1>();
        else if (t + 1 < 16) cp_async_wait<0>();
        __syncthreads();
        buf = (buf == 2) ? 0 : buf + 1;
    }

    // ---- epilogue: normalize, write fp16 ----
    float inv0 = 1.0f / l0, inv1 = 1.0f / l1;
    size_t rowA = (qrow0 + wq + r0) * EMB;
    size_t rowB = rowA + (size_t)8 * EMB;
    #pragma unroll
    for (int j = 0; j < 8; j++) {
        int col = h * DHEAD + j * 8 + c0;
        __half2 hv0, hv1;
        hv0.x = __float2half_rn(o[j][0] * inv0);
        hv0.y = __float2half_rn(o[j][1] * inv0);
        hv1.x = __float2half_rn(o[j][2] * inv1);
        hv1.y = __float2half_rn(o[j][3] * inv1);
        *(__half2*)(atth + rowA + col) = hv0;
        *(__half2*)(atth + rowB + col) = hv1;
    }
}

// ---------------------------------------------------------------------------
extern "C" void kernel_launch(void* const* d_in, const int* in_sizes, int n_in,
                              void* d_out, int out_size)
{
    const float* x    = (const float*)d_in[0];
    const float* Wqkv = (const float*)d_in[1];
    const float* ab   = (const float*)d_in[2];
    const float* Wout = (const float*)d_in[4];
    const float* bout = (const float*)d_in[5];
    float* out = (float*)d_out;

    __half *xh, *wqkvh, *wouth, *qkvh, *atth;
    cudaGetSymbolAddress((void**)&xh, g_xh);
    cudaGetSymbolAddress((void**)&wqkvh, g_wqkvh);
    cudaGetSymbolAddress((void**)&wouth, g_wouth);
    cudaGetSymbolAddress((void**)&qkvh, g_qkvh);
    cudaGetSymbolAddress((void**)&atth, g_atth);

    const int M = BATCH * NTOK;
    const size_t nx = (size_t)M * EMB;
    const size_t nw = (size_t)3 * EMB * EMB;
    const size_t no = (size_t)EMB * EMB;

    cvt_f32h<<<(int)(nx / 4 / 256), 256>>>(x, xh, (int)nx);
    cvt_f32h<<<(int)(nw / 4 / 256), 256>>>(Wqkv, wqkvh, (int)nw);
    cvt_f32h<<<(int)(no / 4 / 256), 256>>>(Wout, wouth, (int)no);

    const int GSMEM = 98304;   // 3-stage x 32KB -> 2 CTAs/SM
    cudaFuncSetAttribute(gemm_mma, cudaFuncAttributeMaxDynamicSharedMemorySize, GSMEM);

    // QKV projection -> fp16
    gemm_mma<<<dim3(3 * EMB / 128, M / 128), 256, GSMEM>>>(
        xh, wqkvh, nullptr, nullptr, qkvh, M, 3 * EMB, 0, 1);

    // attention -> fp16 (analytic bias, no bidx)
    const int ASMEM = 4096 + 3 * 16384;   // 53248
    cudaFuncSetAttribute(attn_mma, cudaFuncAttributeMaxDynamicSharedMemorySize, ASMEM);
    attn_mma<<<dim3(NTOK / 128, HEADS, BATCH), 256, ASMEM>>>(qkvh, ab, atth);

    // output projection (f32 + bias)
    gemm_mma<<<dim3(EMB / 128, M / 128), 256, GSMEM>>>(
        atth, wouth, bout, out, nullptr, M, EMB, 1, 0);
}